// round 5
// baseline (speedup 1.0000x reference)
#include <cuda_runtime.h>
#include <cuda_bf16.h>
#include <cstdint>
#include <math.h>

#define BB 4
#define NN 2048
#define DIMM 512
#define TT 16
#define HH 8
#define DHH 64
#define ROWS (BB*NN)          // 8192
#define QKVN (3*HH*DHH)       // 1536
#define HDSZ (BB*HH*NN*DHH)

typedef __nv_bfloat16 bf16;

// ---------------- scratch (static device globals) ----------------
__device__ bf16 g_xnh[ROWS*DIMM], g_xnl[ROWS*DIMM];
__device__ bf16 g_wqh[QKVN*DIMM], g_wql[QKVN*DIMM];   // W_qkv^T [1536][512]
__device__ bf16 g_woh[DIMM*DIMM], g_wol[DIMM*DIMM];   // W_out^T [512][512]
__device__ bf16 g_qh[HDSZ], g_ql[HDSZ];
__device__ bf16 g_kh[HDSZ], g_kl[HDSZ];
__device__ bf16 g_vh[HDSZ], g_vl[HDSZ];
__device__ bf16 g_ah[ROWS*DIMM], g_al[ROWS*DIMM];     // attention out hi/lo

// ---------------- helpers ----------------
__device__ __forceinline__ uint32_t swz(uint32_t o) { return o ^ ((o >> 3) & 0x70u); }

__device__ __forceinline__ uint32_t smem_u32(const void* p) {
    uint32_t a;
    asm("{ .reg .u64 t; cvta.to.shared.u64 t, %1; cvt.u32.u64 %0, t; }" : "=r"(a) : "l"(p));
    return a;
}

__device__ __forceinline__ uint32_t pack2(float lo, float hi) {
    uint32_t r;
    asm("cvt.rn.bf16x2.f32 %0, %1, %2;" : "=r"(r) : "f"(hi), "f"(lo));
    return r;
}
__device__ __forceinline__ void split_pack(float f0, float f1, uint32_t& hp, uint32_t& lp) {
    float h0 = __bfloat162float(__float2bfloat16(f0));
    float h1 = __bfloat162float(__float2bfloat16(f1));
    hp = pack2(h0, h1);
    lp = pack2(f0 - h0, f1 - h1);
}
__device__ __forceinline__ float ex2f(float x) {
    float y;
    asm("ex2.approx.f32 %0, %1;" : "=f"(y) : "f"(x));
    return y;
}

__device__ __forceinline__ void ldsm_x4(uint32_t* r, uint32_t addr) {
    asm volatile("ldmatrix.sync.aligned.m8n8.x4.shared.b16 {%0,%1,%2,%3}, [%4];"
        : "=r"(r[0]), "=r"(r[1]), "=r"(r[2]), "=r"(r[3]) : "r"(addr));
}
__device__ __forceinline__ void ldsm_x4t(uint32_t* r, uint32_t addr) {
    asm volatile("ldmatrix.sync.aligned.m8n8.x4.trans.shared.b16 {%0,%1,%2,%3}, [%4];"
        : "=r"(r[0]), "=r"(r[1]), "=r"(r[2]), "=r"(r[3]) : "r"(addr));
}
__device__ __forceinline__ void mma16816(float* c, const uint32_t* a, const uint32_t* b) {
    asm volatile("mma.sync.aligned.m16n8k16.row.col.f32.bf16.bf16.f32 "
        "{%0,%1,%2,%3}, {%4,%5,%6,%7}, {%8,%9}, {%0,%1,%2,%3};"
        : "+f"(c[0]), "+f"(c[1]), "+f"(c[2]), "+f"(c[3])
        : "r"(a[0]), "r"(a[1]), "r"(a[2]), "r"(a[3]), "r"(b[0]), "r"(b[1]));
}
__device__ __forceinline__ void cp16(uint32_t dst, const void* src) {
    asm volatile("cp.async.cg.shared.global [%0], [%1], 16;" :: "r"(dst), "l"(src) : "memory");
}
#define CP_COMMIT() asm volatile("cp.async.commit_group;" ::: "memory")
#define CP_WAIT1()  asm volatile("cp.async.wait_group 1;" ::: "memory")
#define CP_WAIT0()  asm volatile("cp.async.wait_group 0;" ::: "memory")

// ---------------- LayerNorm -> bf16 hi/lo ----------------
__global__ void __launch_bounds__(256) ln_kernel(const float* __restrict__ x,
                                                 const float* __restrict__ gamma,
                                                 const float* __restrict__ beta,
                                                 bf16* __restrict__ xnh,
                                                 bf16* __restrict__ xnl)
{
    int row = blockIdx.x;
    int t = threadIdx.x;
    const float2* xr = (const float2*)(x + (size_t)row * DIMM);
    float2 v = xr[t];
    float s = v.x + v.y, ss = v.x*v.x + v.y*v.y;
    #pragma unroll
    for (int o = 16; o > 0; o >>= 1) {
        s  += __shfl_xor_sync(0xffffffffu, s,  o);
        ss += __shfl_xor_sync(0xffffffffu, ss, o);
    }
    __shared__ float ws[8], wss[8];
    int w = t >> 5, lane = t & 31;
    if (lane == 0) { ws[w] = s; wss[w] = ss; }
    __syncthreads();
    if (w == 0) {
        s  = (lane < 8) ? ws[lane]  : 0.f;
        ss = (lane < 8) ? wss[lane] : 0.f;
        #pragma unroll
        for (int o = 4; o > 0; o >>= 1) {
            s  += __shfl_xor_sync(0xffffffffu, s,  o);
            ss += __shfl_xor_sync(0xffffffffu, ss, o);
        }
        if (lane == 0) { ws[0] = s; wss[0] = ss; }
    }
    __syncthreads();
    s = ws[0]; ss = wss[0];
    float mu  = s * (1.0f / DIMM);
    float var = ss * (1.0f / DIMM) - mu * mu;
    float inv = rsqrtf(var + 1e-5f);
    float2 g = ((const float2*)gamma)[t];
    float2 be = ((const float2*)beta)[t];
    float o0 = (v.x - mu) * inv * g.x + be.x;
    float o1 = (v.y - mu) * inv * g.y + be.y;
    uint32_t hp, lp;
    split_pack(o0, o1, hp, lp);
    ((uint32_t*)(xnh + (size_t)row * DIMM))[t] = hp;
    ((uint32_t*)(xnl + (size_t)row * DIMM))[t] = lp;
}

// ---------------- coalesced transpose + hi/lo split ----------------
__global__ void __launch_bounds__(256) wtrans_kernel(const float* __restrict__ W,
                                                     bf16* __restrict__ oh,
                                                     bf16* __restrict__ ol,
                                                     int Kd, int Nd)
{
    __shared__ float t[32][33];
    int tx = threadIdx.x, ty = threadIdx.y;
    int n0 = blockIdx.x * 32, k0 = blockIdx.y * 32;
    #pragma unroll
    for (int i = 0; i < 4; i++)
        t[ty + 8 * i][tx] = W[(size_t)(k0 + ty + 8 * i) * Nd + n0 + tx];
    __syncthreads();
    #pragma unroll
    for (int i = 0; i < 4; i++) {
        int n = n0 + ty + 8 * i, k = k0 + tx;
        float v = t[tx][ty + 8 * i];
        bf16 h = __float2bfloat16(v);
        oh[(size_t)n * Kd + k] = h;
        ol[(size_t)n * Kd + k] = __float2bfloat16(v - __bfloat162float(h));
    }
}

// ---------------- HMMA GEMM: C[M,N] = A[M,K] @ B[N,K]^T, 3-term hi/lo ----------------
// CTA 128x256, 8 warps (2x4), warp tile 64x64, K chunk 64, 2-stage cp.async.
#define GA_H 0
#define GA_L 16384
#define GB_H 32768
#define GB_L 65536
#define GSTAGE 98304
#define GEMM_SMEM (2*GSTAGE)   // 196608

template<bool SCATTER>
__global__ void __launch_bounds__(256)
mma_gemm(const bf16* __restrict__ Ah, const bf16* __restrict__ Al,
         const bf16* __restrict__ Bh, const bf16* __restrict__ Bl,
         float* __restrict__ C, int Ncols, int K,
         bf16* qh, bf16* ql, bf16* kh, bf16* kl, bf16* vh, bf16* vl)
{
    extern __shared__ char smc[];
    uint32_t sb = smem_u32(smc);
    int tid = threadIdx.x, lane = tid & 31, wid = tid >> 5;
    int n0 = blockIdx.x * 256, m0 = blockIdx.y * 128;
    int m0w = (wid >> 2) * 64, n0w = (wid & 3) * 64;

    const bf16* srcA[2] = {Ah + (size_t)m0 * K, Al + (size_t)m0 * K};
    const bf16* srcB[2] = {Bh + (size_t)n0 * K, Bl + (size_t)n0 * K};

    auto load_chunk = [&](int kc, int st) {
        uint32_t base = sb + st * GSTAGE;
        int kofs = kc * 64;
        #pragma unroll
        for (int t = 0; t < 2; t++) {
            const bf16* s = srcA[t] + kofs;
            #pragma unroll
            for (int i = 0; i < 4; i++) {
                int u = tid + i * 256;
                int row = u >> 3, g = u & 7;
                cp16(base + GA_H + t * 16384 + swz(row * 128 + g * 16),
                     s + (size_t)row * K + g * 8);
            }
        }
        #pragma unroll
        for (int t = 0; t < 2; t++) {
            const bf16* s = srcB[t] + kofs;
            #pragma unroll
            for (int i = 0; i < 8; i++) {
                int u = tid + i * 256;
                int row = u >> 3, g = u & 7;
                cp16(base + GB_H + t * 32768 + swz(row * 128 + g * 16),
                     s + (size_t)row * K + g * 8);
            }
        }
        CP_COMMIT();
    };

    float acc[4][8][4];
    #pragma unroll
    for (int a = 0; a < 4; a++)
        #pragma unroll
        for (int b = 0; b < 8; b++)
            #pragma unroll
            for (int c = 0; c < 4; c++) acc[a][b][c] = 0.f;

    int nch = K >> 6;
    load_chunk(0, 0);
    if (nch > 1) load_chunk(1, 1);
    for (int kc = 0; kc < nch; kc++) {
        if (kc + 1 < nch) { CP_WAIT1(); } else { CP_WAIT0(); }
        __syncthreads();
        uint32_t bs = sb + (kc & 1) * GSTAGE;
        #pragma unroll
        for (int kt = 0; kt < 4; kt++) {
            uint32_t afh[4][4], afl[4][4];
            #pragma unroll
            for (int mt = 0; mt < 4; mt++) {
                uint32_t byte = swz((m0w + mt * 16 + (lane & 15)) * 128 +
                                    kt * 32 + (lane >> 4) * 16);
                ldsm_x4(afh[mt], bs + GA_H + byte);
                ldsm_x4(afl[mt], bs + GA_L + byte);
            }
            #pragma unroll
            for (int p = 0; p < 4; p++) {
                uint32_t byte = swz((n0w + p * 16 + (lane & 7) + ((lane >> 4) << 3)) * 128 +
                                    kt * 32 + ((lane >> 3) & 1) * 16);
                uint32_t bfh[4], bfl[4];
                ldsm_x4(bfh, bs + GB_H + byte);
                ldsm_x4(bfl, bs + GB_L + byte);
                #pragma unroll
                for (int mt = 0; mt < 4; mt++)
                    #pragma unroll
                    for (int half = 0; half < 2; half++) {
                        int nt = p * 2 + half;
                        mma16816(acc[mt][nt], afh[mt], &bfh[half * 2]);
                        mma16816(acc[mt][nt], afh[mt], &bfl[half * 2]);
                        mma16816(acc[mt][nt], afl[mt], &bfh[half * 2]);
                    }
            }
        }
        if (kc + 2 < nch) { __syncthreads(); load_chunk(kc + 2, kc & 1); }
    }

    // epilogue
    int rbase = m0 + m0w + (lane >> 2);
    int cbase = n0 + n0w + 2 * (lane & 3);
    #pragma unroll
    for (int mt = 0; mt < 4; mt++) {
        #pragma unroll
        for (int nt = 0; nt < 8; nt++) {
            #pragma unroll
            for (int half = 0; half < 2; half++) {
                int r = rbase + mt * 16 + half * 8;
                int cc = cbase + nt * 8;
                float f0 = acc[mt][nt][half * 2], f1 = acc[mt][nt][half * 2 + 1];
                if (SCATTER) {
                    uint32_t hp, lp;
                    split_pack(f0, f1, hp, lp);
                    int b = r >> 11, n = r & 2047;
                    int part = cc >> 9, h = (cc >> 6) & 7, d = cc & 63;
                    size_t idx = (((size_t)(b * HH + h)) * NN + n) * DHH + d;
                    bf16 *dh, *dl;
                    if (part == 0)      { dh = qh; dl = ql; }
                    else if (part == 1) { dh = kh; dl = kl; }
                    else                { dh = vh; dl = vl; }
                    *(uint32_t*)(dh + idx) = hp;
                    *(uint32_t*)(dl + idx) = lp;
                } else {
                    float2 o2; o2.x = f0; o2.y = f1;
                    *(float2*)(C + (size_t)r * Ncols + cc) = o2;
                }
            }
        }
    }
}

// ---------------- HMMA flash attention, chunk-pipelined ----------------
// 8 warps; warp w owns q-rows [w*16, w*16+16). Q frags hoisted to regs.
// 3-stage KV ring; inner loop: S-MMA(c+1) issued before exp(c)+PV(c).
#define FQ 0
#define FKV 32768
#define FSTAGE 65536
#define FLASH_SMEM (FKV + 3*FSTAGE)   // 229376

__global__ void __launch_bounds__(256)
flash_mma(const bf16* __restrict__ qh, const bf16* __restrict__ ql,
          const bf16* __restrict__ kh, const bf16* __restrict__ kl,
          const bf16* __restrict__ vh, const bf16* __restrict__ vl,
          const float* __restrict__ Rg,
          const float* __restrict__ avec, const float* __restrict__ cvec,
          bf16* __restrict__ ah, bf16* __restrict__ al)
{
    extern __shared__ char smc[];
    uint32_t sb = smem_u32(smc);
    int tid = threadIdx.x, lane = tid & 31, wid = tid >> 5;
    int bid = blockIdx.x;
    int qt = bid & 15, h = (bid >> 4) & 7, b = bid >> 7;
    int bh = b * HH + h;

    float aa = fabsf(avec[h]);
    float ca = fabsf(cvec[h]);

    auto load_kv = [&](int jt, int st) {
        size_t o = ((size_t)bh * NN + jt * 128) * DHH;
        const bf16* s4[4] = {kh + o, kl + o, vh + o, vl + o};
        uint32_t base = sb + FKV + st * FSTAGE;
        #pragma unroll
        for (int t = 0; t < 4; t++) {
            #pragma unroll
            for (int i = 0; i < 4; i++) {
                int u = tid + i * 256;
                int row = u >> 3, g = u & 7;
                cp16(base + t * 16384 + swz(row * 128 + g * 16),
                     s4[t] + (size_t)row * DHH + g * 8);
            }
        }
        CP_COMMIT();
    };

    // Q tiles -> smem (bundled into group 0 with kv0)
    {
        size_t qo = ((size_t)bh * NN + qt * 128) * DHH;
        const bf16* s2[2] = {qh + qo, ql + qo};
        #pragma unroll
        for (int t = 0; t < 2; t++) {
            #pragma unroll
            for (int i = 0; i < 4; i++) {
                int u = tid + i * 256;
                int row = u >> 3, g = u & 7;
                cp16(sb + FQ + t * 16384 + swz(row * 128 + g * 16),
                     s2[t] + (size_t)row * DHH + g * 8);
            }
        }
    }
    load_kv(0, 0);
    load_kv(1, 1);

    CP_WAIT1();
    __syncthreads();

    // hoist Q fragments to registers
    uint32_t qa[4][4], qal[4][4];
    #pragma unroll
    for (int kt = 0; kt < 4; kt++) {
        uint32_t abyte = swz((wid * 16 + (lane & 15)) * 128 +
                             kt * 32 + (lane >> 4) * 16);
        ldsm_x4(qa[kt],  sb + FQ + abyte);
        ldsm_x4(qal[kt], sb + FQ + 16384 + abyte);
    }

    float oacc[8][4];
    #pragma unroll
    for (int i = 0; i < 8; i++)
        #pragma unroll
        for (int j = 0; j < 4; j++) oacc[i][j] = 0.f;
    float rsum_lo = 0.f, rsum_hi = 0.f;

    float sacc[2][4][4];

    for (int jt = 0; jt < 16; jt++) {
        if (jt > 0) {
            if (jt + 1 < 16) { CP_WAIT1(); } else { CP_WAIT0(); }
            __syncthreads();
        }
        if (jt + 2 < 16) load_kv(jt + 2, (jt + 2) % 3);

        uint32_t bKh = sb + FKV + (jt % 3) * FSTAGE;
        uint32_t bKl = bKh + 16384, bVh = bKh + 32768, bVl = bKh + 49152;

        float rb = Rg[((size_t)b * TT + qt) * TT + jt];
        float dscale = (1.f / (1.f + __expf(aa * rb - ca))) * 0.125f * 1.44269504f;

        // S-MMA of one 32-col chunk into sacc[buf]
        auto chunkS = [&](int c, float (*sa)[4]) {
            #pragma unroll
            for (int i = 0; i < 4; i++)
                #pragma unroll
                for (int j = 0; j < 4; j++) sa[i][j] = 0.f;
            #pragma unroll
            for (int kt = 0; kt < 4; kt++) {
                #pragma unroll
                for (int pp = 0; pp < 2; pp++) {
                    int p16 = c * 2 + pp;
                    uint32_t bbyte = swz((p16 * 16 + (lane & 7) + ((lane >> 4) << 3)) * 128 +
                                         kt * 32 + ((lane >> 3) & 1) * 16);
                    uint32_t kb[4], kbl[4];
                    ldsm_x4(kb,  bKh + bbyte);
                    ldsm_x4(kbl, bKl + bbyte);
                    #pragma unroll
                    for (int half = 0; half < 2; half++) {
                        int nt = pp * 2 + half;
                        mma16816(sa[nt], qa[kt],  &kb[half * 2]);
                        mma16816(sa[nt], qa[kt],  &kbl[half * 2]);
                        mma16816(sa[nt], qal[kt], &kb[half * 2]);
                    }
                }
            }
        };

        // exp + PV of one 32-col chunk
        auto chunkEPV = [&](int c, float (*sa)[4]) {
            #pragma unroll
            for (int nt = 0; nt < 4; nt++) {
                #pragma unroll
                for (int r = 0; r < 4; r++) {
                    float p = ex2f(fmaxf(sa[nt][r], 0.f) * dscale);
                    sa[nt][r] = p;
                    if (r < 2) rsum_lo += p; else rsum_hi += p;
                }
            }
            #pragma unroll
            for (int k2 = 0; k2 < 2; k2++) {
                int ktg = c * 2 + k2;
                uint32_t pah[4], pal[4];
                split_pack(sa[2*k2][0],   sa[2*k2][1],   pah[0], pal[0]);
                split_pack(sa[2*k2][2],   sa[2*k2][3],   pah[1], pal[1]);
                split_pack(sa[2*k2+1][0], sa[2*k2+1][1], pah[2], pal[2]);
                split_pack(sa[2*k2+1][2], sa[2*k2+1][3], pah[3], pal[3]);
                #pragma unroll
                for (int p = 0; p < 4; p++) {
                    uint32_t vbyte = swz((ktg * 16 + (lane & 7) + ((lane >> 3) & 1) * 8) * 128 +
                                         p * 32 + (lane >> 4) * 16);
                    uint32_t vb[4], vbl[4];
                    ldsm_x4t(vb,  bVh + vbyte);
                    ldsm_x4t(vbl, bVl + vbyte);
                    #pragma unroll
                    for (int half = 0; half < 2; half++) {
                        int nt = 2 * p + half;
                        mma16816(oacc[nt], pah, &vb[half * 2]);
                        mma16816(oacc[nt], pah, &vbl[half * 2]);
                        mma16816(oacc[nt], pal, &vb[half * 2]);
                    }
                }
            }
        };

        // software pipeline: S(c+1) issued before exp(c)+PV(c)
        chunkS(0, sacc[0]);
        #pragma unroll
        for (int c = 0; c < 4; c++) {
            if (c < 3) chunkS(c + 1, sacc[(c + 1) & 1]);
            chunkEPV(c, sacc[c & 1]);
        }
    }

    // reduce row-sums across the quad
    rsum_lo += __shfl_xor_sync(0xffffffffu, rsum_lo, 1);
    rsum_lo += __shfl_xor_sync(0xffffffffu, rsum_lo, 2);
    rsum_hi += __shfl_xor_sync(0xffffffffu, rsum_hi, 1);
    rsum_hi += __shfl_xor_sync(0xffffffffu, rsum_hi, 2);

    // epilogue
    float inv_lo = 1.f / rsum_lo, inv_hi = 1.f / rsum_hi;
    int r0 = qt * 128 + wid * 16 + (lane >> 2);
    bf16* oh = ah + ((size_t)b * NN + r0) * DIMM + h * DHH;
    bf16* ol = al + ((size_t)b * NN + r0) * DIMM + h * DHH;
    #pragma unroll
    for (int nt = 0; nt < 8; nt++) {
        int c = nt * 8 + 2 * (lane & 3);
        uint32_t hp, lp;
        split_pack(oacc[nt][0] * inv_lo, oacc[nt][1] * inv_lo, hp, lp);
        *(uint32_t*)(oh + c) = hp;
        *(uint32_t*)(ol + c) = lp;
        split_pack(oacc[nt][2] * inv_hi, oacc[nt][3] * inv_hi, hp, lp);
        *(uint32_t*)(oh + (size_t)8 * DIMM + c) = hp;
        *(uint32_t*)(ol + (size_t)8 * DIMM + c) = lp;
    }
}

// ---------------- launch ----------------
extern "C" void kernel_launch(void* const* d_in, const int* in_sizes, int n_in,
                              void* d_out, int out_size)
{
    const float* x     = (const float*)d_in[0];
    const float* R     = (const float*)d_in[1];
    const float* gamma = (const float*)d_in[2];
    const float* beta  = (const float*)d_in[3];
    const float* Wqkv  = (const float*)d_in[4];
    const float* Wout  = (const float*)d_in[5];
    const float* av    = (const float*)d_in[6];
    const float* cv    = (const float*)d_in[7];
    float* out = (float*)d_out;

    bf16 *xnh, *xnl, *wqh, *wql, *woh, *wol;
    bf16 *qh, *ql, *kh, *kl, *vh, *vl, *ah, *al;
    cudaGetSymbolAddress((void**)&xnh, g_xnh); cudaGetSymbolAddress((void**)&xnl, g_xnl);
    cudaGetSymbolAddress((void**)&wqh, g_wqh); cudaGetSymbolAddress((void**)&wql, g_wql);
    cudaGetSymbolAddress((void**)&woh, g_woh); cudaGetSymbolAddress((void**)&wol, g_wol);
    cudaGetSymbolAddress((void**)&qh, g_qh);   cudaGetSymbolAddress((void**)&ql, g_ql);
    cudaGetSymbolAddress((void**)&kh, g_kh);   cudaGetSymbolAddress((void**)&kl, g_kl);
    cudaGetSymbolAddress((void**)&vh, g_vh);   cudaGetSymbolAddress((void**)&vl, g_vl);
    cudaGetSymbolAddress((void**)&ah, g_ah);   cudaGetSymbolAddress((void**)&al, g_al);

    cudaFuncSetAttribute(mma_gemm<true>,  cudaFuncAttributeMaxDynamicSharedMemorySize, GEMM_SMEM);
    cudaFuncSetAttribute(mma_gemm<false>, cudaFuncAttributeMaxDynamicSharedMemorySize, GEMM_SMEM);
    cudaFuncSetAttribute(flash_mma, cudaFuncAttributeMaxDynamicSharedMemorySize, FLASH_SMEM);

    // 1) LayerNorm -> bf16 hi/lo
    ln_kernel<<<ROWS, 256>>>(x, gamma, beta, xnh, xnl);

    // 2) weight transpose + split (coalesced)
    wtrans_kernel<<<dim3(QKVN / 32, DIMM / 32), dim3(32, 8)>>>(Wqkv, wqh, wql, DIMM, QKVN);
    wtrans_kernel<<<dim3(DIMM / 32, DIMM / 32), dim3(32, 8)>>>(Wout, woh, wol, DIMM, DIMM);

    // 3) QKV projection, scatter to q/k/v hi/lo  (grid 6x64 = 384 CTAs)
    mma_gemm<true><<<dim3(QKVN / 256, ROWS / 128), 256, GEMM_SMEM>>>(
        xnh, xnl, wqh, wql, nullptr, QKVN, DIMM, qh, ql, kh, kl, vh, vl);

    // 4) flash attention
    flash_mma<<<BB * HH * 16, 256, FLASH_SMEM>>>(qh, ql, kh, kl, vh, vl,
                                                 R, av, cv, ah, al);

    // 5) output projection -> d_out fp32  (grid 2x64 = 128 CTAs, single wave)
    mma_gemm<false><<<dim3(DIMM / 256, ROWS / 128), 256, GEMM_SMEM>>>(
        ah, al, woh, wol, out, DIMM, DIMM,
        nullptr, nullptr, nullptr, nullptr, nullptr, nullptr);
}

// round 6
// speedup vs baseline: 1.0754x; 1.0754x over previous
#include <cuda_runtime.h>
#include <cuda_bf16.h>
#include <cstdint>
#include <math.h>

#define BB 4
#define NN 2048
#define DIMM 512
#define TT 16
#define HH 8
#define DHH 64
#define ROWS (BB*NN)          // 8192
#define QKVN (3*HH*DHH)       // 1536
#define HDSZ (BB*HH*NN*DHH)

typedef __nv_bfloat16 bf16;

// ---------------- scratch (static device globals) ----------------
__device__ bf16 g_xnh[ROWS*DIMM], g_xnl[ROWS*DIMM];
__device__ bf16 g_wqh[QKVN*DIMM], g_wql[QKVN*DIMM];   // W_qkv^T [1536][512]
__device__ bf16 g_woh[DIMM*DIMM], g_wol[DIMM*DIMM];   // W_out^T [512][512]
__device__ bf16 g_qh[HDSZ], g_ql[HDSZ];
__device__ bf16 g_kh[HDSZ], g_kl[HDSZ];
__device__ bf16 g_vh[HDSZ], g_vl[HDSZ];
__device__ bf16 g_ah[ROWS*DIMM], g_al[ROWS*DIMM];     // attention out hi/lo

// ---------------- helpers ----------------
__device__ __forceinline__ uint32_t swz(uint32_t o) { return o ^ ((o >> 3) & 0x70u); }

__device__ __forceinline__ uint32_t smem_u32(const void* p) {
    uint32_t a;
    asm("{ .reg .u64 t; cvta.to.shared.u64 t, %1; cvt.u32.u64 %0, t; }" : "=r"(a) : "l"(p));
    return a;
}

__device__ __forceinline__ uint32_t pack2(float lo, float hi) {
    uint32_t r;
    asm("cvt.rn.bf16x2.f32 %0, %1, %2;" : "=r"(r) : "f"(hi), "f"(lo));
    return r;
}
__device__ __forceinline__ void split_pack(float f0, float f1, uint32_t& hp, uint32_t& lp) {
    float h0 = __bfloat162float(__float2bfloat16(f0));
    float h1 = __bfloat162float(__float2bfloat16(f1));
    hp = pack2(h0, h1);
    lp = pack2(f0 - h0, f1 - h1);
}
__device__ __forceinline__ float ex2f(float x) {
    float y;
    asm("ex2.approx.f32 %0, %1;" : "=f"(y) : "f"(x));
    return y;
}

__device__ __forceinline__ void ldsm_x4(uint32_t* r, uint32_t addr) {
    asm volatile("ldmatrix.sync.aligned.m8n8.x4.shared.b16 {%0,%1,%2,%3}, [%4];"
        : "=r"(r[0]), "=r"(r[1]), "=r"(r[2]), "=r"(r[3]) : "r"(addr));
}
__device__ __forceinline__ void ldsm_x4t(uint32_t* r, uint32_t addr) {
    asm volatile("ldmatrix.sync.aligned.m8n8.x4.trans.shared.b16 {%0,%1,%2,%3}, [%4];"
        : "=r"(r[0]), "=r"(r[1]), "=r"(r[2]), "=r"(r[3]) : "r"(addr));
}
__device__ __forceinline__ void mma16816(float* c, const uint32_t* a, const uint32_t* b) {
    asm volatile("mma.sync.aligned.m16n8k16.row.col.f32.bf16.bf16.f32 "
        "{%0,%1,%2,%3}, {%4,%5,%6,%7}, {%8,%9}, {%0,%1,%2,%3};"
        : "+f"(c[0]), "+f"(c[1]), "+f"(c[2]), "+f"(c[3])
        : "r"(a[0]), "r"(a[1]), "r"(a[2]), "r"(a[3]), "r"(b[0]), "r"(b[1]));
}
__device__ __forceinline__ void cp16(uint32_t dst, const void* src) {
    asm volatile("cp.async.cg.shared.global [%0], [%1], 16;" :: "r"(dst), "l"(src) : "memory");
}
#define CP_COMMIT() asm volatile("cp.async.commit_group;" ::: "memory")
#define CP_WAIT1()  asm volatile("cp.async.wait_group 1;" ::: "memory")
#define CP_WAIT0()  asm volatile("cp.async.wait_group 0;" ::: "memory")

// ---------------- LayerNorm -> bf16 hi/lo ----------------
__global__ void __launch_bounds__(256) ln_kernel(const float* __restrict__ x,
                                                 const float* __restrict__ gamma,
                                                 const float* __restrict__ beta,
                                                 bf16* __restrict__ xnh,
                                                 bf16* __restrict__ xnl)
{
    int row = blockIdx.x;
    int t = threadIdx.x;
    const float2* xr = (const float2*)(x + (size_t)row * DIMM);
    float2 v = xr[t];
    float s = v.x + v.y, ss = v.x*v.x + v.y*v.y;
    #pragma unroll
    for (int o = 16; o > 0; o >>= 1) {
        s  += __shfl_xor_sync(0xffffffffu, s,  o);
        ss += __shfl_xor_sync(0xffffffffu, ss, o);
    }
    __shared__ float ws[8], wss[8];
    int w = t >> 5, lane = t & 31;
    if (lane == 0) { ws[w] = s; wss[w] = ss; }
    __syncthreads();
    if (w == 0) {
        s  = (lane < 8) ? ws[lane]  : 0.f;
        ss = (lane < 8) ? wss[lane] : 0.f;
        #pragma unroll
        for (int o = 4; o > 0; o >>= 1) {
            s  += __shfl_xor_sync(0xffffffffu, s,  o);
            ss += __shfl_xor_sync(0xffffffffu, ss, o);
        }
        if (lane == 0) { ws[0] = s; wss[0] = ss; }
    }
    __syncthreads();
    s = ws[0]; ss = wss[0];
    float mu  = s * (1.0f / DIMM);
    float var = ss * (1.0f / DIMM) - mu * mu;
    float inv = rsqrtf(var + 1e-5f);
    float2 g = ((const float2*)gamma)[t];
    float2 be = ((const float2*)beta)[t];
    float o0 = (v.x - mu) * inv * g.x + be.x;
    float o1 = (v.y - mu) * inv * g.y + be.y;
    uint32_t hp, lp;
    split_pack(o0, o1, hp, lp);
    ((uint32_t*)(xnh + (size_t)row * DIMM))[t] = hp;
    ((uint32_t*)(xnl + (size_t)row * DIMM))[t] = lp;
}

// ---------------- coalesced transpose + hi/lo split ----------------
__global__ void __launch_bounds__(256) wtrans_kernel(const float* __restrict__ W,
                                                     bf16* __restrict__ oh,
                                                     bf16* __restrict__ ol,
                                                     int Kd, int Nd)
{
    __shared__ float t[32][33];
    int tx = threadIdx.x, ty = threadIdx.y;
    int n0 = blockIdx.x * 32, k0 = blockIdx.y * 32;
    #pragma unroll
    for (int i = 0; i < 4; i++)
        t[ty + 8 * i][tx] = W[(size_t)(k0 + ty + 8 * i) * Nd + n0 + tx];
    __syncthreads();
    #pragma unroll
    for (int i = 0; i < 4; i++) {
        int n = n0 + ty + 8 * i, k = k0 + tx;
        float v = t[tx][ty + 8 * i];
        bf16 h = __float2bfloat16(v);
        oh[(size_t)n * Kd + k] = h;
        ol[(size_t)n * Kd + k] = __float2bfloat16(v - __bfloat162float(h));
    }
}

// ---------------- HMMA GEMM: C[M,N] = A[M,K] @ B[N,K]^T, 3-term hi/lo ----------------
// CTA 128x128, 8 warps (2x4, warp tile 64x32). K chunk 32.
// SMEM rows are [hi 64B | lo 64B] interleaved -> stage 32KB, 2 stages = 64KB
// -> 2 CTAs/SM (with <=128 regs via launch_bounds).
#define GA 0
#define GB 16384
#define GSTAGE 32768
#define GEMM_SMEM (2*GSTAGE)   // 65536

template<bool SCATTER>
__global__ void __launch_bounds__(256, 2)
mma_gemm(const bf16* __restrict__ Ah, const bf16* __restrict__ Al,
         const bf16* __restrict__ Bh, const bf16* __restrict__ Bl,
         float* __restrict__ C, int Ncols, int K,
         bf16* qh, bf16* ql, bf16* kh, bf16* kl, bf16* vh, bf16* vl)
{
    extern __shared__ char smc[];
    uint32_t sb = smem_u32(smc);
    int tid = threadIdx.x, lane = tid & 31, wid = tid >> 5;
    int n0 = blockIdx.x * 128, m0 = blockIdx.y * 128;
    int m0w = (wid >> 2) * 64, n0w = (wid & 3) * 32;

    const bf16* srcA[2] = {Ah + (size_t)m0 * K, Al + (size_t)m0 * K};
    const bf16* srcB[2] = {Bh + (size_t)n0 * K, Bl + (size_t)n0 * K};

    // stage layout: A rows 128 x [hi 64B | lo 64B]; B same.
    auto load_chunk = [&](int kc, int st) {
        uint32_t base = sb + st * GSTAGE;
        int kofs = kc * 32;
        #pragma unroll
        for (int i = 0; i < 4; i++) {           // A: 1024 granules
            int u = tid + i * 256;
            int hl = u >> 9, v = u & 511;
            int row = v >> 2, g = v & 3;
            cp16(base + GA + swz(row * 128 + hl * 64 + g * 16),
                 srcA[hl] + (size_t)row * K + kofs + g * 8);
        }
        #pragma unroll
        for (int i = 0; i < 4; i++) {           // B: 1024 granules
            int u = tid + i * 256;
            int hl = u >> 9, v = u & 511;
            int row = v >> 2, g = v & 3;
            cp16(base + GB + swz(row * 128 + hl * 64 + g * 16),
                 srcB[hl] + (size_t)row * K + kofs + g * 8);
        }
        CP_COMMIT();
    };

    float acc[4][4][4];
    #pragma unroll
    for (int a = 0; a < 4; a++)
        #pragma unroll
        for (int b = 0; b < 4; b++)
            #pragma unroll
            for (int c = 0; c < 4; c++) acc[a][b][c] = 0.f;

    int nch = K >> 5;                 // K/32
    load_chunk(0, 0);
    if (nch > 1) load_chunk(1, 1);
    for (int kc = 0; kc < nch; kc++) {
        if (kc + 1 < nch) { CP_WAIT1(); } else { CP_WAIT0(); }
        __syncthreads();
        uint32_t bs = sb + (kc & 1) * GSTAGE;
        #pragma unroll
        for (int kt = 0; kt < 2; kt++) {
            uint32_t afh[4][4], afl[4][4];
            #pragma unroll
            for (int mt = 0; mt < 4; mt++) {
                uint32_t rowb = (m0w + mt * 16 + (lane & 15)) * 128 +
                                kt * 32 + (lane >> 4) * 16;
                ldsm_x4(afh[mt], bs + GA + swz(rowb));
                ldsm_x4(afl[mt], bs + GA + swz(rowb + 64));
            }
            #pragma unroll
            for (int p = 0; p < 2; p++) {
                uint32_t rowb = (n0w + p * 16 + (lane & 7) + ((lane >> 4) << 3)) * 128 +
                                kt * 32 + ((lane >> 3) & 1) * 16;
                uint32_t bfh[4], bfl[4];
                ldsm_x4(bfh, bs + GB + swz(rowb));
                ldsm_x4(bfl, bs + GB + swz(rowb + 64));
                #pragma unroll
                for (int mt = 0; mt < 4; mt++)
                    #pragma unroll
                    for (int half = 0; half < 2; half++) {
                        int nt = p * 2 + half;
                        mma16816(acc[mt][nt], afh[mt], &bfh[half * 2]);
                        mma16816(acc[mt][nt], afh[mt], &bfl[half * 2]);
                        mma16816(acc[mt][nt], afl[mt], &bfh[half * 2]);
                    }
            }
        }
        __syncthreads();
        if (kc + 2 < nch) load_chunk(kc + 2, kc & 1);
    }

    // epilogue
    int rbase = m0 + m0w + (lane >> 2);
    int cbase = n0 + n0w + 2 * (lane & 3);
    #pragma unroll
    for (int mt = 0; mt < 4; mt++) {
        #pragma unroll
        for (int nt = 0; nt < 4; nt++) {
            #pragma unroll
            for (int half = 0; half < 2; half++) {
                int r = rbase + mt * 16 + half * 8;
                int cc = cbase + nt * 8;
                float f0 = acc[mt][nt][half * 2], f1 = acc[mt][nt][half * 2 + 1];
                if (SCATTER) {
                    uint32_t hp, lp;
                    split_pack(f0, f1, hp, lp);
                    int b = r >> 11, n = r & 2047;
                    int part = cc >> 9, h = (cc >> 6) & 7, d = cc & 63;
                    size_t idx = (((size_t)(b * HH + h)) * NN + n) * DHH + d;
                    bf16 *dh, *dl;
                    if (part == 0)      { dh = qh; dl = ql; }
                    else if (part == 1) { dh = kh; dl = kl; }
                    else                { dh = vh; dl = vl; }
                    *(uint32_t*)(dh + idx) = hp;
                    *(uint32_t*)(dl + idx) = lp;
                } else {
                    float2 o2; o2.x = f0; o2.y = f1;
                    *(float2*)(C + (size_t)r * Ncols + cc) = o2;
                }
            }
        }
    }
}

// ---------------- HMMA flash attention ----------------
// 8 warps; warp w owns q-rows [w*16, w*16+16). Q frags in regs.
// KV tiles of 64 rows, 2-stage ring -> smem 96KB -> 2 CTAs/SM.
#define FQ 0
#define FKV 32768
#define FSTAGE 32768           // K hi/lo + V hi/lo, 64 rows each = 4 x 8KB
#define FLASH_SMEM (FKV + 2*FSTAGE)   // 98304

__global__ void __launch_bounds__(256, 2)
flash_mma(const bf16* __restrict__ qh, const bf16* __restrict__ ql,
          const bf16* __restrict__ kh, const bf16* __restrict__ kl,
          const bf16* __restrict__ vh, const bf16* __restrict__ vl,
          const float* __restrict__ Rg,
          const float* __restrict__ avec, const float* __restrict__ cvec,
          bf16* __restrict__ ah, bf16* __restrict__ al)
{
    extern __shared__ char smc[];
    uint32_t sb = smem_u32(smc);
    int tid = threadIdx.x, lane = tid & 31, wid = tid >> 5;
    int bid = blockIdx.x;
    int qt = bid & 15, h = (bid >> 4) & 7, b = bid >> 7;
    int bh = b * HH + h;

    float aa = fabsf(avec[h]);
    float ca = fabsf(cvec[h]);

    // 64-row KV tile -> 4 matrices x 512 granules = 2048 = 8/thread
    auto load_kv = [&](int jt, int st) {
        size_t o = ((size_t)bh * NN + jt * 64) * DHH;
        const bf16* s4[4] = {kh + o, kl + o, vh + o, vl + o};
        uint32_t base = sb + FKV + st * FSTAGE;
        #pragma unroll
        for (int t = 0; t < 4; t++) {
            #pragma unroll
            for (int i = 0; i < 2; i++) {
                int u = tid + i * 256;
                int row = u >> 3, g = u & 7;
                cp16(base + t * 8192 + swz(row * 128 + g * 16),
                     s4[t] + (size_t)row * DHH + g * 8);
            }
        }
        CP_COMMIT();
    };

    // Q tiles -> smem (bundled into group 0 with kv0)
    {
        size_t qo = ((size_t)bh * NN + qt * 128) * DHH;
        const bf16* s2[2] = {qh + qo, ql + qo};
        #pragma unroll
        for (int t = 0; t < 2; t++) {
            #pragma unroll
            for (int i = 0; i < 4; i++) {
                int u = tid + i * 256;
                int row = u >> 3, g = u & 7;
                cp16(sb + FQ + t * 16384 + swz(row * 128 + g * 16),
                     s2[t] + (size_t)row * DHH + g * 8);
            }
        }
    }
    load_kv(0, 0);
    load_kv(1, 1);

    CP_WAIT1();
    __syncthreads();

    // hoist Q fragments to registers
    uint32_t qa[4][4], qal[4][4];
    #pragma unroll
    for (int kt = 0; kt < 4; kt++) {
        uint32_t abyte = swz((wid * 16 + (lane & 15)) * 128 +
                             kt * 32 + (lane >> 4) * 16);
        ldsm_x4(qa[kt],  sb + FQ + abyte);
        ldsm_x4(qal[kt], sb + FQ + 16384 + abyte);
    }

    float oacc[8][4];
    #pragma unroll
    for (int i = 0; i < 8; i++)
        #pragma unroll
        for (int j = 0; j < 4; j++) oacc[i][j] = 0.f;
    float rsum_lo = 0.f, rsum_hi = 0.f;

    for (int jt = 0; jt < 32; jt++) {
        if (jt > 0) {
            if (jt + 1 < 32) { CP_WAIT1(); } else { CP_WAIT0(); }
            __syncthreads();
        }
        uint32_t bKh = sb + FKV + (jt & 1) * FSTAGE;
        uint32_t bKl = bKh + 8192, bVh = bKh + 16384, bVl = bKh + 24576;

        float rb = Rg[((size_t)b * TT + qt) * TT + (jt >> 1)];
        float dscale = (1.f / (1.f + __expf(aa * rb - ca))) * 0.125f * 1.44269504f;

        // ---- S = Q(16x64) @ K(64x64)^T
        float sacc[8][4];
        #pragma unroll
        for (int i = 0; i < 8; i++)
            #pragma unroll
            for (int j = 0; j < 4; j++) sacc[i][j] = 0.f;

        #pragma unroll
        for (int kt = 0; kt < 4; kt++) {
            #pragma unroll
            for (int p = 0; p < 4; p++) {
                uint32_t bbyte = swz((p * 16 + (lane & 7) + ((lane >> 4) << 3)) * 128 +
                                     kt * 32 + ((lane >> 3) & 1) * 16);
                uint32_t kb[4], kbl[4];
                ldsm_x4(kb,  bKh + bbyte);
                ldsm_x4(kbl, bKl + bbyte);
                #pragma unroll
                for (int half = 0; half < 2; half++) {
                    int nt = 2 * p + half;
                    mma16816(sacc[nt], qa[kt],  &kb[half * 2]);
                    mma16816(sacc[nt], qa[kt],  &kbl[half * 2]);
                    mma16816(sacc[nt], qal[kt], &kb[half * 2]);
                }
            }
        }

        // ---- softmax numerator (bounded logits: no max subtraction)
        #pragma unroll
        for (int nt = 0; nt < 8; nt++) {
            #pragma unroll
            for (int r = 0; r < 4; r++) {
                float p = ex2f(fmaxf(sacc[nt][r], 0.f) * dscale);
                sacc[nt][r] = p;
                if (r < 2) rsum_lo += p; else rsum_hi += p;
            }
        }

        // ---- O += P(16x64) @ V(64x64)
        #pragma unroll
        for (int ktg = 0; ktg < 4; ktg++) {
            uint32_t pah[4], pal[4];
            split_pack(sacc[2*ktg][0],   sacc[2*ktg][1],   pah[0], pal[0]);
            split_pack(sacc[2*ktg][2],   sacc[2*ktg][3],   pah[1], pal[1]);
            split_pack(sacc[2*ktg+1][0], sacc[2*ktg+1][1], pah[2], pal[2]);
            split_pack(sacc[2*ktg+1][2], sacc[2*ktg+1][3], pah[3], pal[3]);
            #pragma unroll
            for (int p = 0; p < 4; p++) {
                uint32_t vbyte = swz((ktg * 16 + (lane & 7) + ((lane >> 3) & 1) * 8) * 128 +
                                     p * 32 + (lane >> 4) * 16);
                uint32_t vb[4], vbl[4];
                ldsm_x4t(vb,  bVh + vbyte);
                ldsm_x4t(vbl, bVl + vbyte);
                #pragma unroll
                for (int half = 0; half < 2; half++) {
                    int nt = 2 * p + half;
                    mma16816(oacc[nt], pah, &vb[half * 2]);
                    mma16816(oacc[nt], pah, &vbl[half * 2]);
                    mma16816(oacc[nt], pal, &vb[half * 2]);
                }
            }
        }

        __syncthreads();
        if (jt + 2 < 32) load_kv(jt + 2, jt & 1);
    }

    // reduce row-sums across the quad
    rsum_lo += __shfl_xor_sync(0xffffffffu, rsum_lo, 1);
    rsum_lo += __shfl_xor_sync(0xffffffffu, rsum_lo, 2);
    rsum_hi += __shfl_xor_sync(0xffffffffu, rsum_hi, 1);
    rsum_hi += __shfl_xor_sync(0xffffffffu, rsum_hi, 2);

    // epilogue
    float inv_lo = 1.f / rsum_lo, inv_hi = 1.f / rsum_hi;
    int r0 = qt * 128 + wid * 16 + (lane >> 2);
    bf16* oh = ah + ((size_t)b * NN + r0) * DIMM + h * DHH;
    bf16* ol = al + ((size_t)b * NN + r0) * DIMM + h * DHH;
    #pragma unroll
    for (int nt = 0; nt < 8; nt++) {
        int c = nt * 8 + 2 * (lane & 3);
        uint32_t hp, lp;
        split_pack(oacc[nt][0] * inv_lo, oacc[nt][1] * inv_lo, hp, lp);
        *(uint32_t*)(oh + c) = hp;
        *(uint32_t*)(ol + c) = lp;
        split_pack(oacc[nt][2] * inv_hi, oacc[nt][3] * inv_hi, hp, lp);
        *(uint32_t*)(oh + (size_t)8 * DIMM + c) = hp;
        *(uint32_t*)(ol + (size_t)8 * DIMM + c) = lp;
    }
}

// ---------------- launch ----------------
extern "C" void kernel_launch(void* const* d_in, const int* in_sizes, int n_in,
                              void* d_out, int out_size)
{
    const float* x     = (const float*)d_in[0];
    const float* R     = (const float*)d_in[1];
    const float* gamma = (const float*)d_in[2];
    const float* beta  = (const float*)d_in[3];
    const float* Wqkv  = (const float*)d_in[4];
    const float* Wout  = (const float*)d_in[5];
    const float* av    = (const float*)d_in[6];
    const float* cv    = (const float*)d_in[7];
    float* out = (float*)d_out;

    bf16 *xnh, *xnl, *wqh, *wql, *woh, *wol;
    bf16 *qh, *ql, *kh, *kl, *vh, *vl, *ah, *al;
    cudaGetSymbolAddress((void**)&xnh, g_xnh); cudaGetSymbolAddress((void**)&xnl, g_xnl);
    cudaGetSymbolAddress((void**)&wqh, g_wqh); cudaGetSymbolAddress((void**)&wql, g_wql);
    cudaGetSymbolAddress((void**)&woh, g_woh); cudaGetSymbolAddress((void**)&wol, g_wol);
    cudaGetSymbolAddress((void**)&qh, g_qh);   cudaGetSymbolAddress((void**)&ql, g_ql);
    cudaGetSymbolAddress((void**)&kh, g_kh);   cudaGetSymbolAddress((void**)&kl, g_kl);
    cudaGetSymbolAddress((void**)&vh, g_vh);   cudaGetSymbolAddress((void**)&vl, g_vl);
    cudaGetSymbolAddress((void**)&ah, g_ah);   cudaGetSymbolAddress((void**)&al, g_al);

    cudaFuncSetAttribute(mma_gemm<true>,  cudaFuncAttributeMaxDynamicSharedMemorySize, GEMM_SMEM);
    cudaFuncSetAttribute(mma_gemm<false>, cudaFuncAttributeMaxDynamicSharedMemorySize, GEMM_SMEM);
    cudaFuncSetAttribute(flash_mma, cudaFuncAttributeMaxDynamicSharedMemorySize, FLASH_SMEM);

    // 1) LayerNorm -> bf16 hi/lo
    ln_kernel<<<ROWS, 256>>>(x, gamma, beta, xnh, xnl);

    // 2) weight transpose + split (coalesced)
    wtrans_kernel<<<dim3(QKVN / 32, DIMM / 32), dim3(32, 8)>>>(Wqkv, wqh, wql, DIMM, QKVN);
    wtrans_kernel<<<dim3(DIMM / 32, DIMM / 32), dim3(32, 8)>>>(Wout, woh, wol, DIMM, DIMM);

    // 3) QKV projection, scatter to q/k/v hi/lo (768 CTAs, 2/SM)
    mma_gemm<true><<<dim3(QKVN / 128, ROWS / 128), 256, GEMM_SMEM>>>(
        xnh, xnl, wqh, wql, nullptr, QKVN, DIMM, qh, ql, kh, kl, vh, vl);

    // 4) flash attention (512 CTAs, 2/SM)
    flash_mma<<<BB * HH * 16, 256, FLASH_SMEM>>>(qh, ql, kh, kl, vh, vl,
                                                 R, av, cv, ah, al);

    // 5) output projection -> d_out fp32 (256 CTAs, 2/SM)
    mma_gemm<false><<<dim3(DIMM / 128, ROWS / 128), 256, GEMM_SMEM>>>(
        ah, al, woh, wol, out, DIMM, DIMM,
        nullptr, nullptr, nullptr, nullptr, nullptr, nullptr);
}

// round 7
// speedup vs baseline: 1.5269x; 1.4198x over previous
#include <cuda_runtime.h>
#include <cuda_fp16.h>
#include <cstdint>
#include <math.h>

#define BB 4
#define NN 2048
#define DIMM 512
#define TT 16
#define HH 8
#define DHH 64
#define ROWS (BB*NN)          // 8192
#define QKVN (3*HH*DHH)       // 1536
#define HDSZ (BB*HH*NN*DHH)

typedef __half f16;

// ---------------- scratch (static device globals) ----------------
__device__ f16 g_xnh[ROWS*DIMM], g_xnl[ROWS*DIMM];   // layernorm out, exact split
__device__ f16 g_wq[QKVN*DIMM];                      // W_qkv^T single fp16
__device__ f16 g_wo[DIMM*DIMM];                      // W_out^T single fp16
__device__ f16 g_qh[HDSZ], g_ql[HDSZ];               // Q exact split
__device__ f16 g_k[HDSZ], g_v[HDSZ];                 // K, V single fp16
__device__ f16 g_ah[ROWS*DIMM], g_al[ROWS*DIMM];     // attention out split

// ---------------- helpers ----------------
__device__ __forceinline__ uint32_t swz(uint32_t o) { return o ^ ((o >> 3) & 0x70u); }

__device__ __forceinline__ uint32_t smem_u32(const void* p) {
    uint32_t a;
    asm("{ .reg .u64 t; cvta.to.shared.u64 t, %1; cvt.u32.u64 %0, t; }" : "=r"(a) : "l"(p));
    return a;
}

__device__ __forceinline__ uint32_t pack2h(float lo, float hi) {
    uint32_t r;
    asm("cvt.rn.f16x2.f32 %0, %1, %2;" : "=r"(r) : "f"(hi), "f"(lo));
    return r;
}
// exact hi/lo split: hi = f16(x), lo = f16(x - hi)  (lo error ~eps^2, negligible)
__device__ __forceinline__ void split_pack(float f0, float f1, uint32_t& hp, uint32_t& lp) {
    float h0 = __half2float(__float2half(f0));
    float h1 = __half2float(__float2half(f1));
    hp = pack2h(h0, h1);
    lp = pack2h(f0 - h0, f1 - h1);
}
__device__ __forceinline__ float ex2f(float x) {
    float y;
    asm("ex2.approx.f32 %0, %1;" : "=f"(y) : "f"(x));
    return y;
}

__device__ __forceinline__ void ldsm_x4(uint32_t* r, uint32_t addr) {
    asm volatile("ldmatrix.sync.aligned.m8n8.x4.shared.b16 {%0,%1,%2,%3}, [%4];"
        : "=r"(r[0]), "=r"(r[1]), "=r"(r[2]), "=r"(r[3]) : "r"(addr));
}
__device__ __forceinline__ void ldsm_x4t(uint32_t* r, uint32_t addr) {
    asm volatile("ldmatrix.sync.aligned.m8n8.x4.trans.shared.b16 {%0,%1,%2,%3}, [%4];"
        : "=r"(r[0]), "=r"(r[1]), "=r"(r[2]), "=r"(r[3]) : "r"(addr));
}
__device__ __forceinline__ void mma16816(float* c, const uint32_t* a, const uint32_t* b) {
    asm volatile("mma.sync.aligned.m16n8k16.row.col.f32.f16.f16.f32 "
        "{%0,%1,%2,%3}, {%4,%5,%6,%7}, {%8,%9}, {%0,%1,%2,%3};"
        : "+f"(c[0]), "+f"(c[1]), "+f"(c[2]), "+f"(c[3])
        : "r"(a[0]), "r"(a[1]), "r"(a[2]), "r"(a[3]), "r"(b[0]), "r"(b[1]));
}
__device__ __forceinline__ void cp16(uint32_t dst, const void* src) {
    asm volatile("cp.async.cg.shared.global [%0], [%1], 16;" :: "r"(dst), "l"(src) : "memory");
}
#define CP_COMMIT() asm volatile("cp.async.commit_group;" ::: "memory")
#define CP_WAIT1()  asm volatile("cp.async.wait_group 1;" ::: "memory")
#define CP_WAIT0()  asm volatile("cp.async.wait_group 0;" ::: "memory")

// ---------------- LayerNorm -> fp16 hi/lo ----------------
__global__ void __launch_bounds__(256) ln_kernel(const float* __restrict__ x,
                                                 const float* __restrict__ gamma,
                                                 const float* __restrict__ beta,
                                                 f16* __restrict__ xnh,
                                                 f16* __restrict__ xnl)
{
    int row = blockIdx.x;
    int t = threadIdx.x;
    const float2* xr = (const float2*)(x + (size_t)row * DIMM);
    float2 v = xr[t];
    float s = v.x + v.y, ss = v.x*v.x + v.y*v.y;
    #pragma unroll
    for (int o = 16; o > 0; o >>= 1) {
        s  += __shfl_xor_sync(0xffffffffu, s,  o);
        ss += __shfl_xor_sync(0xffffffffu, ss, o);
    }
    __shared__ float ws[8], wss[8];
    int w = t >> 5, lane = t & 31;
    if (lane == 0) { ws[w] = s; wss[w] = ss; }
    __syncthreads();
    if (w == 0) {
        s  = (lane < 8) ? ws[lane]  : 0.f;
        ss = (lane < 8) ? wss[lane] : 0.f;
        #pragma unroll
        for (int o = 4; o > 0; o >>= 1) {
            s  += __shfl_xor_sync(0xffffffffu, s,  o);
            ss += __shfl_xor_sync(0xffffffffu, ss, o);
        }
        if (lane == 0) { ws[0] = s; wss[0] = ss; }
    }
    __syncthreads();
    s = ws[0]; ss = wss[0];
    float mu  = s * (1.0f / DIMM);
    float var = ss * (1.0f / DIMM) - mu * mu;
    float inv = rsqrtf(var + 1e-5f);
    float2 g = ((const float2*)gamma)[t];
    float2 be = ((const float2*)beta)[t];
    float o0 = (v.x - mu) * inv * g.x + be.x;
    float o1 = (v.y - mu) * inv * g.y + be.y;
    uint32_t hp, lp;
    split_pack(o0, o1, hp, lp);
    ((uint32_t*)(xnh + (size_t)row * DIMM))[t] = hp;
    ((uint32_t*)(xnl + (size_t)row * DIMM))[t] = lp;
}

// ---------------- coalesced transpose -> single fp16 ----------------
__global__ void __launch_bounds__(256) wtrans_kernel(const float* __restrict__ W,
                                                     f16* __restrict__ oh,
                                                     int Kd, int Nd)
{
    __shared__ float t[32][33];
    int tx = threadIdx.x, ty = threadIdx.y;
    int n0 = blockIdx.x * 32, k0 = blockIdx.y * 32;
    #pragma unroll
    for (int i = 0; i < 4; i++)
        t[ty + 8 * i][tx] = W[(size_t)(k0 + ty + 8 * i) * Nd + n0 + tx];
    __syncthreads();
    #pragma unroll
    for (int i = 0; i < 4; i++) {
        int n = n0 + ty + 8 * i, k = k0 + tx;
        oh[(size_t)n * Kd + k] = __float2half(t[tx][ty + 8 * i]);
    }
}

// ---------------- HMMA GEMM: C[M,N] = (Ah+Al)[M,K] @ B[N,K]^T ----------------
// CTA 128x128, 8 warps (2x4, warp tile 64x32), K chunk 64, 2-stage cp.async.
// stage: Ah 16KB | Al 16KB | B 16KB = 48KB; 2 stages = 96KB -> 2 CTAs/SM.
#define GA_H 0
#define GA_L 16384
#define GB   32768
#define GSTAGE 49152
#define GEMM_SMEM (2*GSTAGE)   // 98304

template<bool SCATTER>
__global__ void __launch_bounds__(256, 2)
mma_gemm(const f16* __restrict__ Ah, const f16* __restrict__ Al,
         const f16* __restrict__ B,
         float* __restrict__ C, int Ncols, int K,
         f16* qh, f16* ql, f16* kv_k, f16* kv_v)
{
    extern __shared__ char smc[];
    uint32_t sb = smem_u32(smc);
    int tid = threadIdx.x, lane = tid & 31, wid = tid >> 5;
    int n0 = blockIdx.x * 128, m0 = blockIdx.y * 128;
    int m0w = (wid >> 2) * 64, n0w = (wid & 3) * 32;

    const f16* srcA[2] = {Ah + (size_t)m0 * K, Al + (size_t)m0 * K};
    const f16* srcB = B + (size_t)n0 * K;

    auto load_chunk = [&](int kc, int st) {
        uint32_t base = sb + st * GSTAGE;
        int kofs = kc * 64;
        #pragma unroll
        for (int t = 0; t < 2; t++) {          // Ah, Al: 1024 granules each
            const f16* s = srcA[t] + kofs;
            #pragma unroll
            for (int i = 0; i < 4; i++) {
                int u = tid + i * 256;
                int row = u >> 3, g = u & 7;
                cp16(base + GA_H + t * 16384 + swz(row * 128 + g * 16),
                     s + (size_t)row * K + g * 8);
            }
        }
        {                                       // B: 1024 granules
            const f16* s = srcB + kofs;
            #pragma unroll
            for (int i = 0; i < 4; i++) {
                int u = tid + i * 256;
                int row = u >> 3, g = u & 7;
                cp16(base + GB + swz(row * 128 + g * 16),
                     s + (size_t)row * K + g * 8);
            }
        }
        CP_COMMIT();
    };

    float acc[4][4][4];
    #pragma unroll
    for (int a = 0; a < 4; a++)
        #pragma unroll
        for (int b = 0; b < 4; b++)
            #pragma unroll
            for (int c = 0; c < 4; c++) acc[a][b][c] = 0.f;

    int nch = K >> 6;
    load_chunk(0, 0);
    if (nch > 1) load_chunk(1, 1);
    for (int kc = 0; kc < nch; kc++) {
        if (kc + 1 < nch) { CP_WAIT1(); } else { CP_WAIT0(); }
        __syncthreads();
        uint32_t bs = sb + (kc & 1) * GSTAGE;
        #pragma unroll
        for (int kt = 0; kt < 4; kt++) {
            uint32_t afh[4][4], afl[4][4];
            #pragma unroll
            for (int mt = 0; mt < 4; mt++) {
                uint32_t byte = swz((m0w + mt * 16 + (lane & 15)) * 128 +
                                    kt * 32 + (lane >> 4) * 16);
                ldsm_x4(afh[mt], bs + GA_H + byte);
                ldsm_x4(afl[mt], bs + GA_L + byte);
            }
            #pragma unroll
            for (int p = 0; p < 2; p++) {
                uint32_t byte = swz((n0w + p * 16 + (lane & 7) + ((lane >> 4) << 3)) * 128 +
                                    kt * 32 + ((lane >> 3) & 1) * 16);
                uint32_t bf[4];
                ldsm_x4(bf, bs + GB + byte);
                #pragma unroll
                for (int mt = 0; mt < 4; mt++)
                    #pragma unroll
                    for (int half = 0; half < 2; half++) {
                        int nt = p * 2 + half;
                        mma16816(acc[mt][nt], afh[mt], &bf[half * 2]);
                        mma16816(acc[mt][nt], afl[mt], &bf[half * 2]);
                    }
            }
        }
        __syncthreads();
        if (kc + 2 < nch) load_chunk(kc + 2, kc & 1);
    }

    // epilogue
    int rbase = m0 + m0w + (lane >> 2);
    int cbase = n0 + n0w + 2 * (lane & 3);
    #pragma unroll
    for (int mt = 0; mt < 4; mt++) {
        #pragma unroll
        for (int nt = 0; nt < 4; nt++) {
            #pragma unroll
            for (int half = 0; half < 2; half++) {
                int r = rbase + mt * 16 + half * 8;
                int cc = cbase + nt * 8;
                float f0 = acc[mt][nt][half * 2], f1 = acc[mt][nt][half * 2 + 1];
                if (SCATTER) {
                    uint32_t hp, lp;
                    split_pack(f0, f1, hp, lp);
                    int b = r >> 11, n = r & 2047;
                    int part = cc >> 9, h = (cc >> 6) & 7, d = cc & 63;
                    size_t idx = (((size_t)(b * HH + h)) * NN + n) * DHH + d;
                    if (part == 0) {            // Q: exact split
                        *(uint32_t*)(qh + idx) = hp;
                        *(uint32_t*)(ql + idx) = lp;
                    } else if (part == 1) {     // K: single fp16
                        *(uint32_t*)(kv_k + idx) = hp;
                    } else {                    // V: single fp16
                        *(uint32_t*)(kv_v + idx) = hp;
                    }
                } else {
                    float2 o2; o2.x = f0; o2.y = f1;
                    *(float2*)(C + (size_t)r * Ncols + cc) = o2;
                }
            }
        }
    }
}

// ---------------- HMMA flash attention (Q split, K/V single fp16) ----------------
// 8 warps; warp w owns q-rows [w*16, w*16+16). Q frags in regs.
// KV tiles of 64 rows, 2-stage ring: stage = K 8KB + V 8KB = 16KB.
// smem total = Q 32KB + 2*16KB = 64KB -> 2 CTAs/SM.
#define FQ 0
#define FKV 32768
#define FSTAGE 16384
#define FLASH_SMEM (FKV + 2*FSTAGE)   // 65536

__global__ void __launch_bounds__(256, 2)
flash_mma(const f16* __restrict__ qh, const f16* __restrict__ ql,
          const f16* __restrict__ kk, const f16* __restrict__ vv,
          const float* __restrict__ Rg,
          const float* __restrict__ avec, const float* __restrict__ cvec,
          f16* __restrict__ ah, f16* __restrict__ al)
{
    extern __shared__ char smc[];
    uint32_t sb = smem_u32(smc);
    int tid = threadIdx.x, lane = tid & 31, wid = tid >> 5;
    int bid = blockIdx.x;
    int qt = bid & 15, h = (bid >> 4) & 7, b = bid >> 7;
    int bh = b * HH + h;

    float aa = fabsf(avec[h]);
    float ca = fabsf(cvec[h]);

    // 64-row KV tile: K + V = 2 x 512 granules = 1024 -> 4/thread
    auto load_kv = [&](int jt, int st) {
        size_t o = ((size_t)bh * NN + jt * 64) * DHH;
        const f16* s2[2] = {kk + o, vv + o};
        uint32_t base = sb + FKV + st * FSTAGE;
        #pragma unroll
        for (int t = 0; t < 2; t++) {
            #pragma unroll
            for (int i = 0; i < 2; i++) {
                int u = tid + i * 256;
                int row = u >> 3, g = u & 7;
                cp16(base + t * 8192 + swz(row * 128 + g * 16),
                     s2[t] + (size_t)row * DHH + g * 8);
            }
        }
        CP_COMMIT();
    };

    // Q tiles -> smem (bundled into group 0 with kv0)
    {
        size_t qo = ((size_t)bh * NN + qt * 128) * DHH;
        const f16* s2[2] = {qh + qo, ql + qo};
        #pragma unroll
        for (int t = 0; t < 2; t++) {
            #pragma unroll
            for (int i = 0; i < 4; i++) {
                int u = tid + i * 256;
                int row = u >> 3, g = u & 7;
                cp16(sb + FQ + t * 16384 + swz(row * 128 + g * 16),
                     s2[t] + (size_t)row * DHH + g * 8);
            }
        }
    }
    load_kv(0, 0);
    load_kv(1, 1);

    CP_WAIT1();
    __syncthreads();

    // hoist Q fragments to registers
    uint32_t qa[4][4], qal[4][4];
    #pragma unroll
    for (int kt = 0; kt < 4; kt++) {
        uint32_t abyte = swz((wid * 16 + (lane & 15)) * 128 +
                             kt * 32 + (lane >> 4) * 16);
        ldsm_x4(qa[kt],  sb + FQ + abyte);
        ldsm_x4(qal[kt], sb + FQ + 16384 + abyte);
    }

    float oacc[8][4];
    #pragma unroll
    for (int i = 0; i < 8; i++)
        #pragma unroll
        for (int j = 0; j < 4; j++) oacc[i][j] = 0.f;
    float rsum_lo = 0.f, rsum_hi = 0.f;

    for (int jt = 0; jt < 32; jt++) {
        if (jt > 0) {
            if (jt + 1 < 32) { CP_WAIT1(); } else { CP_WAIT0(); }
            __syncthreads();
        }
        uint32_t bK = sb + FKV + (jt & 1) * FSTAGE;
        uint32_t bV = bK + 8192;

        float rb = Rg[((size_t)b * TT + qt) * TT + (jt >> 1)];
        float dscale = (1.f / (1.f + __expf(aa * rb - ca))) * 0.125f * 1.44269504f;

        // ---- S = (Qh+Ql)(16x64) @ K(64x64)^T
        float sacc[8][4];
        #pragma unroll
        for (int i = 0; i < 8; i++)
            #pragma unroll
            for (int j = 0; j < 4; j++) sacc[i][j] = 0.f;

        #pragma unroll
        for (int kt = 0; kt < 4; kt++) {
            #pragma unroll
            for (int p = 0; p < 4; p++) {
                uint32_t bbyte = swz((p * 16 + (lane & 7) + ((lane >> 4) << 3)) * 128 +
                                     kt * 32 + ((lane >> 3) & 1) * 16);
                uint32_t kb[4];
                ldsm_x4(kb, bK + bbyte);
                #pragma unroll
                for (int half = 0; half < 2; half++) {
                    int nt = 2 * p + half;
                    mma16816(sacc[nt], qa[kt],  &kb[half * 2]);
                    mma16816(sacc[nt], qal[kt], &kb[half * 2]);
                }
            }
        }

        // ---- softmax numerator (bounded logits: no max subtraction)
        #pragma unroll
        for (int nt = 0; nt < 8; nt++) {
            #pragma unroll
            for (int r = 0; r < 4; r++) {
                float p = ex2f(fmaxf(sacc[nt][r], 0.f) * dscale);
                sacc[nt][r] = p;
                if (r < 2) rsum_lo += p; else rsum_hi += p;
            }
        }

        // ---- O += (Ph+Pl)(16x64) @ V(64x64)
        #pragma unroll
        for (int ktg = 0; ktg < 4; ktg++) {
            uint32_t pah[4], pal[4];
            split_pack(sacc[2*ktg][0],   sacc[2*ktg][1],   pah[0], pal[0]);
            split_pack(sacc[2*ktg][2],   sacc[2*ktg][3],   pah[1], pal[1]);
            split_pack(sacc[2*ktg+1][0], sacc[2*ktg+1][1], pah[2], pal[2]);
            split_pack(sacc[2*ktg+1][2], sacc[2*ktg+1][3], pah[3], pal[3]);
            #pragma unroll
            for (int p = 0; p < 4; p++) {
                uint32_t vbyte = swz((ktg * 16 + (lane & 7) + ((lane >> 3) & 1) * 8) * 128 +
                                     p * 32 + (lane >> 4) * 16);
                uint32_t vb[4];
                ldsm_x4t(vb, bV + vbyte);
                #pragma unroll
                for (int half = 0; half < 2; half++) {
                    int nt = 2 * p + half;
                    mma16816(oacc[nt], pah, &vb[half * 2]);
                    mma16816(oacc[nt], pal, &vb[half * 2]);
                }
            }
        }

        __syncthreads();
        if (jt + 2 < 32) load_kv(jt + 2, jt & 1);
    }

    // reduce row-sums across the quad
    rsum_lo += __shfl_xor_sync(0xffffffffu, rsum_lo, 1);
    rsum_lo += __shfl_xor_sync(0xffffffffu, rsum_lo, 2);
    rsum_hi += __shfl_xor_sync(0xffffffffu, rsum_hi, 1);
    rsum_hi += __shfl_xor_sync(0xffffffffu, rsum_hi, 2);

    // epilogue: normalize, exact split, store
    float inv_lo = 1.f / rsum_lo, inv_hi = 1.f / rsum_hi;
    int r0 = qt * 128 + wid * 16 + (lane >> 2);
    f16* oh = ah + ((size_t)b * NN + r0) * DIMM + h * DHH;
    f16* ol = al + ((size_t)b * NN + r0) * DIMM + h * DHH;
    #pragma unroll
    for (int nt = 0; nt < 8; nt++) {
        int c = nt * 8 + 2 * (lane & 3);
        uint32_t hp, lp;
        split_pack(oacc[nt][0] * inv_lo, oacc[nt][1] * inv_lo, hp, lp);
        *(uint32_t*)(oh + c) = hp;
        *(uint32_t*)(ol + c) = lp;
        split_pack(oacc[nt][2] * inv_hi, oacc[nt][3] * inv_hi, hp, lp);
        *(uint32_t*)(oh + (size_t)8 * DIMM + c) = hp;
        *(uint32_t*)(ol + (size_t)8 * DIMM + c) = lp;
    }
}

// ---------------- launch ----------------
extern "C" void kernel_launch(void* const* d_in, const int* in_sizes, int n_in,
                              void* d_out, int out_size)
{
    const float* x     = (const float*)d_in[0];
    const float* R     = (const float*)d_in[1];
    const float* gamma = (const float*)d_in[2];
    const float* beta  = (const float*)d_in[3];
    const float* Wqkv  = (const float*)d_in[4];
    const float* Wout  = (const float*)d_in[5];
    const float* av    = (const float*)d_in[6];
    const float* cv    = (const float*)d_in[7];
    float* out = (float*)d_out;

    f16 *xnh, *xnl, *wq, *wo, *qh, *ql, *kk, *vv, *ah, *al;
    cudaGetSymbolAddress((void**)&xnh, g_xnh); cudaGetSymbolAddress((void**)&xnl, g_xnl);
    cudaGetSymbolAddress((void**)&wq, g_wq);   cudaGetSymbolAddress((void**)&wo, g_wo);
    cudaGetSymbolAddress((void**)&qh, g_qh);   cudaGetSymbolAddress((void**)&ql, g_ql);
    cudaGetSymbolAddress((void**)&kk, g_k);    cudaGetSymbolAddress((void**)&vv, g_v);
    cudaGetSymbolAddress((void**)&ah, g_ah);   cudaGetSymbolAddress((void**)&al, g_al);

    cudaFuncSetAttribute(mma_gemm<true>,  cudaFuncAttributeMaxDynamicSharedMemorySize, GEMM_SMEM);
    cudaFuncSetAttribute(mma_gemm<false>, cudaFuncAttributeMaxDynamicSharedMemorySize, GEMM_SMEM);
    cudaFuncSetAttribute(flash_mma, cudaFuncAttributeMaxDynamicSharedMemorySize, FLASH_SMEM);

    // 1) LayerNorm -> fp16 hi/lo
    ln_kernel<<<ROWS, 256>>>(x, gamma, beta, xnh, xnl);

    // 2) weight transpose -> single fp16
    wtrans_kernel<<<dim3(QKVN / 32, DIMM / 32), dim3(32, 8)>>>(Wqkv, wq, DIMM, QKVN);
    wtrans_kernel<<<dim3(DIMM / 32, DIMM / 32), dim3(32, 8)>>>(Wout, wo, DIMM, DIMM);

    // 3) QKV projection (2-term), scatter: Q split, K/V single
    mma_gemm<true><<<dim3(QKVN / 128, ROWS / 128), 256, GEMM_SMEM>>>(
        xnh, xnl, wq, nullptr, QKVN, DIMM, qh, ql, kk, vv);

    // 4) flash attention (2-term)
    flash_mma<<<BB * HH * 16, 256, FLASH_SMEM>>>(qh, ql, kk, vv,
                                                 R, av, cv, ah, al);

    // 5) output projection (2-term) -> d_out fp32
    mma_gemm<false><<<dim3(DIMM / 128, ROWS / 128), 256, GEMM_SMEM>>>(
        ah, al, wo, out, DIMM, DIMM,
        nullptr, nullptr, nullptr, nullptr);
}

// round 8
// speedup vs baseline: 2.1503x; 1.4083x over previous
#include <cuda_runtime.h>
#include <cuda_fp16.h>
#include <cstdint>
#include <math.h>

#define BB 4
#define NN 2048
#define DIMM 512
#define TT 16
#define HH 8
#define DHH 64
#define ROWS (BB*NN)          // 8192
#define QKVN (3*HH*DHH)       // 1536
#define HDSZ (BB*HH*NN*DHH)

typedef __half f16;

// ---------------- scratch (static device globals) ----------------
__device__ f16 g_xnh[ROWS*DIMM], g_xnl[ROWS*DIMM];   // layernorm out, exact split
__device__ f16 g_wq[QKVN*DIMM];                      // W_qkv^T single fp16
__device__ f16 g_wo[DIMM*DIMM];                      // W_out^T single fp16
__device__ f16 g_q[HDSZ], g_k[HDSZ], g_v[HDSZ];      // Q,K,V single fp16
__device__ f16 g_a[ROWS*DIMM];                       // attention out single fp16

// ---------------- helpers ----------------
__device__ __forceinline__ uint32_t swz(uint32_t o) { return o ^ ((o >> 3) & 0x70u); }

__device__ __forceinline__ uint32_t smem_u32(const void* p) {
    uint32_t a;
    asm("{ .reg .u64 t; cvta.to.shared.u64 t, %1; cvt.u32.u64 %0, t; }" : "=r"(a) : "l"(p));
    return a;
}

__device__ __forceinline__ uint32_t pack2h(float lo, float hi) {
    uint32_t r;
    asm("cvt.rn.f16x2.f32 %0, %1, %2;" : "=r"(r) : "f"(hi), "f"(lo));
    return r;
}
// exact hi/lo split for the QKV input path
__device__ __forceinline__ void split_pack(float f0, float f1, uint32_t& hp, uint32_t& lp) {
    float h0 = __half2float(__float2half(f0));
    float h1 = __half2float(__float2half(f1));
    hp = pack2h(h0, h1);
    lp = pack2h(f0 - h0, f1 - h1);
}
__device__ __forceinline__ float ex2f(float x) {
    float y;
    asm("ex2.approx.f32 %0, %1;" : "=f"(y) : "f"(x));
    return y;
}

__device__ __forceinline__ void ldsm_x4(uint32_t* r, uint32_t addr) {
    asm volatile("ldmatrix.sync.aligned.m8n8.x4.shared.b16 {%0,%1,%2,%3}, [%4];"
        : "=r"(r[0]), "=r"(r[1]), "=r"(r[2]), "=r"(r[3]) : "r"(addr));
}
__device__ __forceinline__ void ldsm_x4t(uint32_t* r, uint32_t addr) {
    asm volatile("ldmatrix.sync.aligned.m8n8.x4.trans.shared.b16 {%0,%1,%2,%3}, [%4];"
        : "=r"(r[0]), "=r"(r[1]), "=r"(r[2]), "=r"(r[3]) : "r"(addr));
}
__device__ __forceinline__ void mma16816(float* c, const uint32_t* a, const uint32_t* b) {
    asm volatile("mma.sync.aligned.m16n8k16.row.col.f32.f16.f16.f32 "
        "{%0,%1,%2,%3}, {%4,%5,%6,%7}, {%8,%9}, {%0,%1,%2,%3};"
        : "+f"(c[0]), "+f"(c[1]), "+f"(c[2]), "+f"(c[3])
        : "r"(a[0]), "r"(a[1]), "r"(a[2]), "r"(a[3]), "r"(b[0]), "r"(b[1]));
}
__device__ __forceinline__ void cp16(uint32_t dst, const void* src) {
    asm volatile("cp.async.cg.shared.global [%0], [%1], 16;" :: "r"(dst), "l"(src) : "memory");
}
#define CP_COMMIT() asm volatile("cp.async.commit_group;" ::: "memory")
#define CP_WAIT1()  asm volatile("cp.async.wait_group 1;" ::: "memory")
#define CP_WAIT0()  asm volatile("cp.async.wait_group 0;" ::: "memory")

// ---------------- LayerNorm -> fp16 hi/lo (exact split) ----------------
__global__ void __launch_bounds__(256) ln_kernel(const float* __restrict__ x,
                                                 const float* __restrict__ gamma,
                                                 const float* __restrict__ beta,
                                                 f16* __restrict__ xnh,
                                                 f16* __restrict__ xnl)
{
    int row = blockIdx.x;
    int t = threadIdx.x;
    const float2* xr = (const float2*)(x + (size_t)row * DIMM);
    float2 v = xr[t];
    float s = v.x + v.y, ss = v.x*v.x + v.y*v.y;
    #pragma unroll
    for (int o = 16; o > 0; o >>= 1) {
        s  += __shfl_xor_sync(0xffffffffu, s,  o);
        ss += __shfl_xor_sync(0xffffffffu, ss, o);
    }
    __shared__ float ws[8], wss[8];
    int w = t >> 5, lane = t & 31;
    if (lane == 0) { ws[w] = s; wss[w] = ss; }
    __syncthreads();
    if (w == 0) {
        s  = (lane < 8) ? ws[lane]  : 0.f;
        ss = (lane < 8) ? wss[lane] : 0.f;
        #pragma unroll
        for (int o = 4; o > 0; o >>= 1) {
            s  += __shfl_xor_sync(0xffffffffu, s,  o);
            ss += __shfl_xor_sync(0xffffffffu, ss, o);
        }
        if (lane == 0) { ws[0] = s; wss[0] = ss; }
    }
    __syncthreads();
    s = ws[0]; ss = wss[0];
    float mu  = s * (1.0f / DIMM);
    float var = ss * (1.0f / DIMM) - mu * mu;
    float inv = rsqrtf(var + 1e-5f);
    float2 g = ((const float2*)gamma)[t];
    float2 be = ((const float2*)beta)[t];
    float o0 = (v.x - mu) * inv * g.x + be.x;
    float o1 = (v.y - mu) * inv * g.y + be.y;
    uint32_t hp, lp;
    split_pack(o0, o1, hp, lp);
    ((uint32_t*)(xnh + (size_t)row * DIMM))[t] = hp;
    ((uint32_t*)(xnl + (size_t)row * DIMM))[t] = lp;
}

// ---------------- coalesced transpose -> single fp16 ----------------
__global__ void __launch_bounds__(256) wtrans_kernel(const float* __restrict__ W,
                                                     f16* __restrict__ oh,
                                                     int Kd, int Nd)
{
    __shared__ float t[32][33];
    int tx = threadIdx.x, ty = threadIdx.y;
    int n0 = blockIdx.x * 32, k0 = blockIdx.y * 32;
    #pragma unroll
    for (int i = 0; i < 4; i++)
        t[ty + 8 * i][tx] = W[(size_t)(k0 + ty + 8 * i) * Nd + n0 + tx];
    __syncthreads();
    #pragma unroll
    for (int i = 0; i < 4; i++) {
        int n = n0 + ty + 8 * i, k = k0 + tx;
        oh[(size_t)n * Kd + k] = __float2half(t[tx][ty + 8 * i]);
    }
}

// ---------------- HMMA GEMM: C[M,N] = A[M,K] @ B[N,K]^T ----------------
// SPLIT_A: A = Ah + Al exact split (2-term). CTA 128x128, 8 warps, K chunk 64.
#define GA_H 0
#define GA_L 16384
#define GB   32768
#define GSTAGE 49152
#define GEMM_SMEM (2*GSTAGE)   // 98304

template<bool SCATTER, bool SPLIT_A>
__global__ void __launch_bounds__(256, 2)
mma_gemm(const f16* __restrict__ Ah, const f16* __restrict__ Al,
         const f16* __restrict__ B,
         float* __restrict__ C, int Ncols, int K,
         f16* qo, f16* ko, f16* vo)
{
    extern __shared__ char smc[];
    uint32_t sb = smem_u32(smc);
    int tid = threadIdx.x, lane = tid & 31, wid = tid >> 5;
    int n0 = blockIdx.x * 128, m0 = blockIdx.y * 128;
    int m0w = (wid >> 2) * 64, n0w = (wid & 3) * 32;

    const f16* srcAh = Ah + (size_t)m0 * K;
    const f16* srcAl = SPLIT_A ? (Al + (size_t)m0 * K) : nullptr;
    const f16* srcB  = B + (size_t)n0 * K;

    auto load_chunk = [&](int kc, int st) {
        uint32_t base = sb + st * GSTAGE;
        int kofs = kc * 64;
        #pragma unroll
        for (int i = 0; i < 4; i++) {
            int u = tid + i * 256;
            int row = u >> 3, g = u & 7;
            cp16(base + GA_H + swz(row * 128 + g * 16),
                 srcAh + (size_t)row * K + kofs + g * 8);
        }
        if (SPLIT_A) {
            #pragma unroll
            for (int i = 0; i < 4; i++) {
                int u = tid + i * 256;
                int row = u >> 3, g = u & 7;
                cp16(base + GA_L + swz(row * 128 + g * 16),
                     srcAl + (size_t)row * K + kofs + g * 8);
            }
        }
        #pragma unroll
        for (int i = 0; i < 4; i++) {
            int u = tid + i * 256;
            int row = u >> 3, g = u & 7;
            cp16(base + GB + swz(row * 128 + g * 16),
                 srcB + (size_t)row * K + kofs + g * 8);
        }
        CP_COMMIT();
    };

    float acc[4][4][4];
    #pragma unroll
    for (int a = 0; a < 4; a++)
        #pragma unroll
        for (int b = 0; b < 4; b++)
            #pragma unroll
            for (int c = 0; c < 4; c++) acc[a][b][c] = 0.f;

    int nch = K >> 6;
    load_chunk(0, 0);
    if (nch > 1) load_chunk(1, 1);
    for (int kc = 0; kc < nch; kc++) {
        if (kc + 1 < nch) { CP_WAIT1(); } else { CP_WAIT0(); }
        __syncthreads();
        uint32_t bs = sb + (kc & 1) * GSTAGE;
        #pragma unroll
        for (int kt = 0; kt < 4; kt++) {
            uint32_t afh[4][4], afl[4][4];
            #pragma unroll
            for (int mt = 0; mt < 4; mt++) {
                uint32_t byte = swz((m0w + mt * 16 + (lane & 15)) * 128 +
                                    kt * 32 + (lane >> 4) * 16);
                ldsm_x4(afh[mt], bs + GA_H + byte);
                if (SPLIT_A) ldsm_x4(afl[mt], bs + GA_L + byte);
            }
            #pragma unroll
            for (int p = 0; p < 2; p++) {
                uint32_t byte = swz((n0w + p * 16 + (lane & 7) + ((lane >> 4) << 3)) * 128 +
                                    kt * 32 + ((lane >> 3) & 1) * 16);
                uint32_t bf[4];
                ldsm_x4(bf, bs + GB + byte);
                #pragma unroll
                for (int mt = 0; mt < 4; mt++)
                    #pragma unroll
                    for (int half = 0; half < 2; half++) {
                        int nt = p * 2 + half;
                        mma16816(acc[mt][nt], afh[mt], &bf[half * 2]);
                        if (SPLIT_A) mma16816(acc[mt][nt], afl[mt], &bf[half * 2]);
                    }
            }
        }
        __syncthreads();
        if (kc + 2 < nch) load_chunk(kc + 2, kc & 1);
    }

    // epilogue
    int rbase = m0 + m0w + (lane >> 2);
    int cbase = n0 + n0w + 2 * (lane & 3);
    #pragma unroll
    for (int mt = 0; mt < 4; mt++) {
        #pragma unroll
        for (int nt = 0; nt < 4; nt++) {
            #pragma unroll
            for (int half = 0; half < 2; half++) {
                int r = rbase + mt * 16 + half * 8;
                int cc = cbase + nt * 8;
                float f0 = acc[mt][nt][half * 2], f1 = acc[mt][nt][half * 2 + 1];
                if (SCATTER) {
                    uint32_t hp = pack2h(f0, f1);
                    int b = r >> 11, n = r & 2047;
                    int part = cc >> 9, h = (cc >> 6) & 7, d = cc & 63;
                    size_t idx = (((size_t)(b * HH + h)) * NN + n) * DHH + d;
                    f16* dst = (part == 0) ? qo : ((part == 1) ? ko : vo);
                    *(uint32_t*)(dst + idx) = hp;
                } else {
                    float2 o2; o2.x = f0; o2.y = f1;
                    *(float2*)(C + (size_t)r * Ncols + cc) = o2;
                }
            }
        }
    }
}

// ---------------- HMMA flash attention (all single fp16) ----------------
// 8 warps; warp w owns q-rows [w*16, w*16+16). Q frags in regs.
// KV tiles of 64 rows, 2-stage ring: stage = K 8KB + V 8KB = 16KB.
// smem total = Q 16KB + 2*16KB = 48KB.
#define FQ 0
#define FKV 16384
#define FSTAGE 16384
#define FLASH_SMEM (FKV + 2*FSTAGE)   // 49152

__global__ void __launch_bounds__(256, 2)
flash_mma(const f16* __restrict__ qq, const f16* __restrict__ kk,
          const f16* __restrict__ vv,
          const float* __restrict__ Rg,
          const float* __restrict__ avec, const float* __restrict__ cvec,
          f16* __restrict__ aout)
{
    extern __shared__ char smc[];
    uint32_t sb = smem_u32(smc);
    int tid = threadIdx.x, lane = tid & 31, wid = tid >> 5;
    int bid = blockIdx.x;
    int qt = bid & 15, h = (bid >> 4) & 7, b = bid >> 7;
    int bh = b * HH + h;

    float aa = fabsf(avec[h]);
    float ca = fabsf(cvec[h]);

    auto load_kv = [&](int jt, int st) {
        size_t o = ((size_t)bh * NN + jt * 64) * DHH;
        const f16* s2[2] = {kk + o, vv + o};
        uint32_t base = sb + FKV + st * FSTAGE;
        #pragma unroll
        for (int t = 0; t < 2; t++) {
            #pragma unroll
            for (int i = 0; i < 2; i++) {
                int u = tid + i * 256;
                int row = u >> 3, g = u & 7;
                cp16(base + t * 8192 + swz(row * 128 + g * 16),
                     s2[t] + (size_t)row * DHH + g * 8);
            }
        }
        CP_COMMIT();
    };

    // Q tile -> smem (bundled into group 0 with kv0)
    {
        size_t qo = ((size_t)bh * NN + qt * 128) * DHH;
        #pragma unroll
        for (int i = 0; i < 4; i++) {
            int u = tid + i * 256;
            int row = u >> 3, g = u & 7;
            cp16(sb + FQ + swz(row * 128 + g * 16),
                 qq + qo + (size_t)row * DHH + g * 8);
        }
    }
    load_kv(0, 0);
    load_kv(1, 1);

    CP_WAIT1();
    __syncthreads();

    // hoist Q fragments to registers
    uint32_t qa[4][4];
    #pragma unroll
    for (int kt = 0; kt < 4; kt++) {
        uint32_t abyte = swz((wid * 16 + (lane & 15)) * 128 +
                             kt * 32 + (lane >> 4) * 16);
        ldsm_x4(qa[kt], sb + FQ + abyte);
    }

    float oacc[8][4];
    #pragma unroll
    for (int i = 0; i < 8; i++)
        #pragma unroll
        for (int j = 0; j < 4; j++) oacc[i][j] = 0.f;
    float rsum_lo = 0.f, rsum_hi = 0.f;

    for (int jt = 0; jt < 32; jt++) {
        if (jt > 0) {
            if (jt + 1 < 32) { CP_WAIT1(); } else { CP_WAIT0(); }
            __syncthreads();
        }
        uint32_t bK = sb + FKV + (jt & 1) * FSTAGE;
        uint32_t bV = bK + 8192;

        float rb = Rg[((size_t)b * TT + qt) * TT + (jt >> 1)];
        float dscale = (1.f / (1.f + __expf(aa * rb - ca))) * 0.125f * 1.44269504f;

        // ---- S = Q(16x64) @ K(64x64)^T  (1-term)
        float sacc[8][4];
        #pragma unroll
        for (int i = 0; i < 8; i++)
            #pragma unroll
            for (int j = 0; j < 4; j++) sacc[i][j] = 0.f;

        #pragma unroll
        for (int kt = 0; kt < 4; kt++) {
            #pragma unroll
            for (int p = 0; p < 4; p++) {
                uint32_t bbyte = swz((p * 16 + (lane & 7) + ((lane >> 4) << 3)) * 128 +
                                     kt * 32 + ((lane >> 3) & 1) * 16);
                uint32_t kb[4];
                ldsm_x4(kb, bK + bbyte);
                #pragma unroll
                for (int half = 0; half < 2; half++) {
                    int nt = 2 * p + half;
                    mma16816(sacc[nt], qa[kt], &kb[half * 2]);
                }
            }
        }

        // ---- softmax numerator (bounded logits: no max subtraction)
        #pragma unroll
        for (int nt = 0; nt < 8; nt++) {
            #pragma unroll
            for (int r = 0; r < 4; r++) {
                float p = ex2f(fmaxf(sacc[nt][r], 0.f) * dscale);
                sacc[nt][r] = p;
                if (r < 2) rsum_lo += p; else rsum_hi += p;
            }
        }

        // ---- O += P(16x64) @ V(64x64)  (1-term, P packed fp16)
        #pragma unroll
        for (int ktg = 0; ktg < 4; ktg++) {
            uint32_t pa[4];
            pa[0] = pack2h(sacc[2*ktg][0],   sacc[2*ktg][1]);
            pa[1] = pack2h(sacc[2*ktg][2],   sacc[2*ktg][3]);
            pa[2] = pack2h(sacc[2*ktg+1][0], sacc[2*ktg+1][1]);
            pa[3] = pack2h(sacc[2*ktg+1][2], sacc[2*ktg+1][3]);
            #pragma unroll
            for (int p = 0; p < 4; p++) {
                uint32_t vbyte = swz((ktg * 16 + (lane & 7) + ((lane >> 3) & 1) * 8) * 128 +
                                     p * 32 + (lane >> 4) * 16);
                uint32_t vb[4];
                ldsm_x4t(vb, bV + vbyte);
                #pragma unroll
                for (int half = 0; half < 2; half++) {
                    int nt = 2 * p + half;
                    mma16816(oacc[nt], pa, &vb[half * 2]);
                }
            }
        }

        __syncthreads();
        if (jt + 2 < 32) load_kv(jt + 2, jt & 1);
    }

    // reduce row-sums across the quad
    rsum_lo += __shfl_xor_sync(0xffffffffu, rsum_lo, 1);
    rsum_lo += __shfl_xor_sync(0xffffffffu, rsum_lo, 2);
    rsum_hi += __shfl_xor_sync(0xffffffffu, rsum_hi, 1);
    rsum_hi += __shfl_xor_sync(0xffffffffu, rsum_hi, 2);

    // epilogue: normalize, pack single fp16, store
    float inv_lo = 1.f / rsum_lo, inv_hi = 1.f / rsum_hi;
    int r0 = qt * 128 + wid * 16 + (lane >> 2);
    f16* oh = aout + ((size_t)b * NN + r0) * DIMM + h * DHH;
    #pragma unroll
    for (int nt = 0; nt < 8; nt++) {
        int c = nt * 8 + 2 * (lane & 3);
        *(uint32_t*)(oh + c) =
            pack2h(oacc[nt][0] * inv_lo, oacc[nt][1] * inv_lo);
        *(uint32_t*)(oh + (size_t)8 * DIMM + c) =
            pack2h(oacc[nt][2] * inv_hi, oacc[nt][3] * inv_hi);
    }
}

// ---------------- launch ----------------
extern "C" void kernel_launch(void* const* d_in, const int* in_sizes, int n_in,
                              void* d_out, int out_size)
{
    const float* x     = (const float*)d_in[0];
    const float* R     = (const float*)d_in[1];
    const float* gamma = (const float*)d_in[2];
    const float* beta  = (const float*)d_in[3];
    const float* Wqkv  = (const float*)d_in[4];
    const float* Wout  = (const float*)d_in[5];
    const float* av    = (const float*)d_in[6];
    const float* cv    = (const float*)d_in[7];
    float* out = (float*)d_out;

    f16 *xnh, *xnl, *wq, *wo, *qq, *kk, *vv, *aa;
    cudaGetSymbolAddress((void**)&xnh, g_xnh); cudaGetSymbolAddress((void**)&xnl, g_xnl);
    cudaGetSymbolAddress((void**)&wq, g_wq);   cudaGetSymbolAddress((void**)&wo, g_wo);
    cudaGetSymbolAddress((void**)&qq, g_q);    cudaGetSymbolAddress((void**)&kk, g_k);
    cudaGetSymbolAddress((void**)&vv, g_v);    cudaGetSymbolAddress((void**)&aa, g_a);

    cudaFuncSetAttribute((const void*)mma_gemm<true, true>,
                         cudaFuncAttributeMaxDynamicSharedMemorySize, GEMM_SMEM);
    cudaFuncSetAttribute((const void*)mma_gemm<false, false>,
                         cudaFuncAttributeMaxDynamicSharedMemorySize, GEMM_SMEM);
    cudaFuncSetAttribute((const void*)flash_mma,
                         cudaFuncAttributeMaxDynamicSharedMemorySize, FLASH_SMEM);

    // 1) LayerNorm -> fp16 exact split
    ln_kernel<<<ROWS, 256>>>(x, gamma, beta, xnh, xnl);

    // 2) weight transpose -> single fp16
    wtrans_kernel<<<dim3(QKVN / 32, DIMM / 32), dim3(32, 8)>>>(Wqkv, wq, DIMM, QKVN);
    wtrans_kernel<<<dim3(DIMM / 32, DIMM / 32), dim3(32, 8)>>>(Wout, wo, DIMM, DIMM);

    // 3) QKV projection (2-term A-split), scatter q/k/v single fp16
    mma_gemm<true, true><<<dim3(QKVN / 128, ROWS / 128), 256, GEMM_SMEM>>>(
        xnh, xnl, wq, nullptr, QKVN, DIMM, qq, kk, vv);

    // 4) flash attention (1-term)
    flash_mma<<<BB * HH * 16, 256, FLASH_SMEM>>>(qq, kk, vv, R, av, cv, aa);

    // 5) output projection (1-term) -> d_out fp32
    mma_gemm<false, false><<<dim3(DIMM / 128, ROWS / 128), 256, GEMM_SMEM>>>(
        aa, nullptr, wo, out, DIMM, DIMM, nullptr, nullptr, nullptr);
}

// round 9
// speedup vs baseline: 2.5326x; 1.1778x over previous
#include <cuda_runtime.h>
#include <cuda_fp16.h>
#include <cstdint>
#include <math.h>

#define BB 4
#define NN 2048
#define DIMM 512
#define TT 16
#define HH 8
#define DHH 64
#define ROWS (BB*NN)          // 8192
#define QKVN (3*HH*DHH)       // 1536
#define HDSZ (BB*HH*NN*DHH)

typedef __half f16;

// ---------------- scratch (static device globals) ----------------
__device__ f16 g_xn[ROWS*DIMM];                      // layernorm out fp16
__device__ f16 g_wq[QKVN*DIMM];                      // W_qkv^T fp16
__device__ f16 g_wo[DIMM*DIMM];                      // W_out^T fp16
__device__ f16 g_q[HDSZ], g_k[HDSZ], g_v[HDSZ];      // Q,K,V fp16
__device__ f16 g_a[ROWS*DIMM];                       // attention out fp16

// ---------------- helpers ----------------
__device__ __forceinline__ uint32_t swz(uint32_t o) { return o ^ ((o >> 3) & 0x70u); }

__device__ __forceinline__ uint32_t smem_u32(const void* p) {
    uint32_t a;
    asm("{ .reg .u64 t; cvta.to.shared.u64 t, %1; cvt.u32.u64 %0, t; }" : "=r"(a) : "l"(p));
    return a;
}

__device__ __forceinline__ uint32_t pack2h(float lo, float hi) {
    uint32_t r;
    asm("cvt.rn.f16x2.f32 %0, %1, %2;" : "=r"(r) : "f"(hi), "f"(lo));
    return r;
}
__device__ __forceinline__ float ex2f(float x) {
    float y;
    asm("ex2.approx.f32 %0, %1;" : "=f"(y) : "f"(x));
    return y;
}

__device__ __forceinline__ void ldsm_x4(uint32_t* r, uint32_t addr) {
    asm volatile("ldmatrix.sync.aligned.m8n8.x4.shared.b16 {%0,%1,%2,%3}, [%4];"
        : "=r"(r[0]), "=r"(r[1]), "=r"(r[2]), "=r"(r[3]) : "r"(addr));
}
__device__ __forceinline__ void ldsm_x4t(uint32_t* r, uint32_t addr) {
    asm volatile("ldmatrix.sync.aligned.m8n8.x4.trans.shared.b16 {%0,%1,%2,%3}, [%4];"
        : "=r"(r[0]), "=r"(r[1]), "=r"(r[2]), "=r"(r[3]) : "r"(addr));
}
__device__ __forceinline__ void mma16816(float* c, const uint32_t* a, const uint32_t* b) {
    asm volatile("mma.sync.aligned.m16n8k16.row.col.f32.f16.f16.f32 "
        "{%0,%1,%2,%3}, {%4,%5,%6,%7}, {%8,%9}, {%0,%1,%2,%3};"
        : "+f"(c[0]), "+f"(c[1]), "+f"(c[2]), "+f"(c[3])
        : "r"(a[0]), "r"(a[1]), "r"(a[2]), "r"(a[3]), "r"(b[0]), "r"(b[1]));
}
__device__ __forceinline__ void cp16(uint32_t dst, const void* src) {
    asm volatile("cp.async.cg.shared.global [%0], [%1], 16;" :: "r"(dst), "l"(src) : "memory");
}
#define CP_COMMIT() asm volatile("cp.async.commit_group;" ::: "memory")
#define CP_WAIT1()  asm volatile("cp.async.wait_group 1;" ::: "memory")
#define CP_WAIT0()  asm volatile("cp.async.wait_group 0;" ::: "memory")

// ---------------- LayerNorm -> fp16 ----------------
__global__ void __launch_bounds__(256) ln_kernel(const float* __restrict__ x,
                                                 const float* __restrict__ gamma,
                                                 const float* __restrict__ beta,
                                                 f16* __restrict__ xn)
{
    int row = blockIdx.x;
    int t = threadIdx.x;
    const float2* xr = (const float2*)(x + (size_t)row * DIMM);
    float2 v = xr[t];
    float s = v.x + v.y, ss = v.x*v.x + v.y*v.y;
    #pragma unroll
    for (int o = 16; o > 0; o >>= 1) {
        s  += __shfl_xor_sync(0xffffffffu, s,  o);
        ss += __shfl_xor_sync(0xffffffffu, ss, o);
    }
    __shared__ float ws[8], wss[8];
    int w = t >> 5, lane = t & 31;
    if (lane == 0) { ws[w] = s; wss[w] = ss; }
    __syncthreads();
    if (w == 0) {
        s  = (lane < 8) ? ws[lane]  : 0.f;
        ss = (lane < 8) ? wss[lane] : 0.f;
        #pragma unroll
        for (int o = 4; o > 0; o >>= 1) {
            s  += __shfl_xor_sync(0xffffffffu, s,  o);
            ss += __shfl_xor_sync(0xffffffffu, ss, o);
        }
        if (lane == 0) { ws[0] = s; wss[0] = ss; }
    }
    __syncthreads();
    s = ws[0]; ss = wss[0];
    float mu  = s * (1.0f / DIMM);
    float var = ss * (1.0f / DIMM) - mu * mu;
    float inv = rsqrtf(var + 1e-5f);
    float2 g = ((const float2*)gamma)[t];
    float2 be = ((const float2*)beta)[t];
    float o0 = (v.x - mu) * inv * g.x + be.x;
    float o1 = (v.y - mu) * inv * g.y + be.y;
    ((uint32_t*)(xn + (size_t)row * DIMM))[t] = pack2h(o0, o1);
}

// ---------------- coalesced transpose -> fp16 ----------------
__global__ void __launch_bounds__(256) wtrans_kernel(const float* __restrict__ W,
                                                     f16* __restrict__ oh,
                                                     int Kd, int Nd)
{
    __shared__ float t[32][33];
    int tx = threadIdx.x, ty = threadIdx.y;
    int n0 = blockIdx.x * 32, k0 = blockIdx.y * 32;
    #pragma unroll
    for (int i = 0; i < 4; i++)
        t[ty + 8 * i][tx] = W[(size_t)(k0 + ty + 8 * i) * Nd + n0 + tx];
    __syncthreads();
    #pragma unroll
    for (int i = 0; i < 4; i++) {
        int n = n0 + ty + 8 * i, k = k0 + tx;
        oh[(size_t)n * Kd + k] = __float2half(t[tx][ty + 8 * i]);
    }
}

// ---------------- HMMA GEMM: C[M,N] = A[M,K] @ B[N,K]^T (1-term fp16) ----------------
// CTA 128x128, 8 warps (2x4, warp tile 64x32), K chunk 64, 2-stage cp.async.
// stage: A 16KB + B 16KB = 32KB; 2 stages = 64KB.
#define GA 0
#define GB 16384
#define GSTAGE 32768
#define GEMM_SMEM (2*GSTAGE)   // 65536

template<bool SCATTER>
__global__ void __launch_bounds__(256, 2)
mma_gemm(const f16* __restrict__ A, const f16* __restrict__ B,
         float* __restrict__ C, int Ncols, int K,
         f16* qo, f16* ko, f16* vo)
{
    extern __shared__ char smc[];
    uint32_t sb = smem_u32(smc);
    int tid = threadIdx.x, lane = tid & 31, wid = tid >> 5;
    int n0 = blockIdx.x * 128, m0 = blockIdx.y * 128;
    int m0w = (wid >> 2) * 64, n0w = (wid & 3) * 32;

    const f16* srcA = A + (size_t)m0 * K;
    const f16* srcB = B + (size_t)n0 * K;

    auto load_chunk = [&](int kc, int st) {
        uint32_t base = sb + st * GSTAGE;
        int kofs = kc * 64;
        #pragma unroll
        for (int i = 0; i < 4; i++) {
            int u = tid + i * 256;
            int row = u >> 3, g = u & 7;
            cp16(base + GA + swz(row * 128 + g * 16),
                 srcA + (size_t)row * K + kofs + g * 8);
        }
        #pragma unroll
        for (int i = 0; i < 4; i++) {
            int u = tid + i * 256;
            int row = u >> 3, g = u & 7;
            cp16(base + GB + swz(row * 128 + g * 16),
                 srcB + (size_t)row * K + kofs + g * 8);
        }
        CP_COMMIT();
    };

    float acc[4][4][4];
    #pragma unroll
    for (int a = 0; a < 4; a++)
        #pragma unroll
        for (int b = 0; b < 4; b++)
            #pragma unroll
            for (int c = 0; c < 4; c++) acc[a][b][c] = 0.f;

    int nch = K >> 6;
    load_chunk(0, 0);
    if (nch > 1) load_chunk(1, 1);
    for (int kc = 0; kc < nch; kc++) {
        if (kc + 1 < nch) { CP_WAIT1(); } else { CP_WAIT0(); }
        __syncthreads();
        uint32_t bs = sb + (kc & 1) * GSTAGE;
        #pragma unroll
        for (int kt = 0; kt < 4; kt++) {
            uint32_t af[4][4];
            #pragma unroll
            for (int mt = 0; mt < 4; mt++) {
                uint32_t byte = swz((m0w + mt * 16 + (lane & 15)) * 128 +
                                    kt * 32 + (lane >> 4) * 16);
                ldsm_x4(af[mt], bs + GA + byte);
            }
            #pragma unroll
            for (int p = 0; p < 2; p++) {
                uint32_t byte = swz((n0w + p * 16 + (lane & 7) + ((lane >> 4) << 3)) * 128 +
                                    kt * 32 + ((lane >> 3) & 1) * 16);
                uint32_t bf[4];
                ldsm_x4(bf, bs + GB + byte);
                #pragma unroll
                for (int mt = 0; mt < 4; mt++)
                    #pragma unroll
                    for (int half = 0; half < 2; half++) {
                        int nt = p * 2 + half;
                        mma16816(acc[mt][nt], af[mt], &bf[half * 2]);
                    }
            }
        }
        __syncthreads();
        if (kc + 2 < nch) load_chunk(kc + 2, kc & 1);
    }

    // epilogue
    int rbase = m0 + m0w + (lane >> 2);
    int cbase = n0 + n0w + 2 * (lane & 3);
    #pragma unroll
    for (int mt = 0; mt < 4; mt++) {
        #pragma unroll
        for (int nt = 0; nt < 4; nt++) {
            #pragma unroll
            for (int half = 0; half < 2; half++) {
                int r = rbase + mt * 16 + half * 8;
                int cc = cbase + nt * 8;
                float f0 = acc[mt][nt][half * 2], f1 = acc[mt][nt][half * 2 + 1];
                if (SCATTER) {
                    uint32_t hp = pack2h(f0, f1);
                    int b = r >> 11, n = r & 2047;
                    int part = cc >> 9, h = (cc >> 6) & 7, d = cc & 63;
                    size_t idx = (((size_t)(b * HH + h)) * NN + n) * DHH + d;
                    f16* dst = (part == 0) ? qo : ((part == 1) ? ko : vo);
                    *(uint32_t*)(dst + idx) = hp;
                } else {
                    float2 o2; o2.x = f0; o2.y = f1;
                    *(float2*)(C + (size_t)r * Ncols + cc) = o2;
                }
            }
        }
    }
}

// ---------------- HMMA flash attention (all fp16, 1-term) ----------------
// 8 warps; warp w owns q-rows [w*16, w*16+16). Q frags in regs.
// KV tiles of 64 rows, 2-stage ring: stage = K 8KB + V 8KB = 16KB.
#define FQ 0
#define FKV 16384
#define FSTAGE 16384
#define FLASH_SMEM (FKV + 2*FSTAGE)   // 49152

__global__ void __launch_bounds__(256, 2)
flash_mma(const f16* __restrict__ qq, const f16* __restrict__ kk,
          const f16* __restrict__ vv,
          const float* __restrict__ Rg,
          const float* __restrict__ avec, const float* __restrict__ cvec,
          f16* __restrict__ aout)
{
    extern __shared__ char smc[];
    uint32_t sb = smem_u32(smc);
    int tid = threadIdx.x, lane = tid & 31, wid = tid >> 5;
    int bid = blockIdx.x;
    int qt = bid & 15, h = (bid >> 4) & 7, b = bid >> 7;
    int bh = b * HH + h;

    float aa = fabsf(avec[h]);
    float ca = fabsf(cvec[h]);

    auto load_kv = [&](int jt, int st) {
        size_t o = ((size_t)bh * NN + jt * 64) * DHH;
        const f16* s2[2] = {kk + o, vv + o};
        uint32_t base = sb + FKV + st * FSTAGE;
        #pragma unroll
        for (int t = 0; t < 2; t++) {
            #pragma unroll
            for (int i = 0; i < 2; i++) {
                int u = tid + i * 256;
                int row = u >> 3, g = u & 7;
                cp16(base + t * 8192 + swz(row * 128 + g * 16),
                     s2[t] + (size_t)row * DHH + g * 8);
            }
        }
        CP_COMMIT();
    };

    // Q tile -> smem (bundled into group 0 with kv0)
    {
        size_t qo = ((size_t)bh * NN + qt * 128) * DHH;
        #pragma unroll
        for (int i = 0; i < 4; i++) {
            int u = tid + i * 256;
            int row = u >> 3, g = u & 7;
            cp16(sb + FQ + swz(row * 128 + g * 16),
                 qq + qo + (size_t)row * DHH + g * 8);
        }
    }
    load_kv(0, 0);
    load_kv(1, 1);

    CP_WAIT1();
    __syncthreads();

    // hoist Q fragments to registers
    uint32_t qa[4][4];
    #pragma unroll
    for (int kt = 0; kt < 4; kt++) {
        uint32_t abyte = swz((wid * 16 + (lane & 15)) * 128 +
                             kt * 32 + (lane >> 4) * 16);
        ldsm_x4(qa[kt], sb + FQ + abyte);
    }

    float oacc[8][4];
    #pragma unroll
    for (int i = 0; i < 8; i++)
        #pragma unroll
        for (int j = 0; j < 4; j++) oacc[i][j] = 0.f;
    float rsum_lo = 0.f, rsum_hi = 0.f;

    for (int jt = 0; jt < 32; jt++) {
        if (jt > 0) {
            if (jt + 1 < 32) { CP_WAIT1(); } else { CP_WAIT0(); }
            __syncthreads();
        }
        uint32_t bK = sb + FKV + (jt & 1) * FSTAGE;
        uint32_t bV = bK + 8192;

        float rb = Rg[((size_t)b * TT + qt) * TT + (jt >> 1)];
        float dscale = (1.f / (1.f + __expf(aa * rb - ca))) * 0.125f * 1.44269504f;

        // ---- S = Q(16x64) @ K(64x64)^T
        float sacc[8][4];
        #pragma unroll
        for (int i = 0; i < 8; i++)
            #pragma unroll
            for (int j = 0; j < 4; j++) sacc[i][j] = 0.f;

        #pragma unroll
        for (int kt = 0; kt < 4; kt++) {
            #pragma unroll
            for (int p = 0; p < 4; p++) {
                uint32_t bbyte = swz((p * 16 + (lane & 7) + ((lane >> 4) << 3)) * 128 +
                                     kt * 32 + ((lane >> 3) & 1) * 16);
                uint32_t kb[4];
                ldsm_x4(kb, bK + bbyte);
                #pragma unroll
                for (int half = 0; half < 2; half++) {
                    int nt = 2 * p + half;
                    mma16816(sacc[nt], qa[kt], &kb[half * 2]);
                }
            }
        }

        // ---- softmax numerator (bounded logits: no max subtraction)
        #pragma unroll
        for (int nt = 0; nt < 8; nt++) {
            #pragma unroll
            for (int r = 0; r < 4; r++) {
                float p = ex2f(fmaxf(sacc[nt][r], 0.f) * dscale);
                sacc[nt][r] = p;
                if (r < 2) rsum_lo += p; else rsum_hi += p;
            }
        }

        // ---- O += P(16x64) @ V(64x64)
        #pragma unroll
        for (int ktg = 0; ktg < 4; ktg++) {
            uint32_t pa[4];
            pa[0] = pack2h(sacc[2*ktg][0],   sacc[2*ktg][1]);
            pa[1] = pack2h(sacc[2*ktg][2],   sacc[2*ktg][3]);
            pa[2] = pack2h(sacc[2*ktg+1][0], sacc[2*ktg+1][1]);
            pa[3] = pack2h(sacc[2*ktg+1][2], sacc[2*ktg+1][3]);
            #pragma unroll
            for (int p = 0; p < 4; p++) {
                uint32_t vbyte = swz((ktg * 16 + (lane & 7) + ((lane >> 3) & 1) * 8) * 128 +
                                     p * 32 + (lane >> 4) * 16);
                uint32_t vb[4];
                ldsm_x4t(vb, bV + vbyte);
                #pragma unroll
                for (int half = 0; half < 2; half++) {
                    int nt = 2 * p + half;
                    mma16816(oacc[nt], pa, &vb[half * 2]);
                }
            }
        }

        __syncthreads();
        if (jt + 2 < 32) load_kv(jt + 2, jt & 1);
    }

    // reduce row-sums across the quad
    rsum_lo += __shfl_xor_sync(0xffffffffu, rsum_lo, 1);
    rsum_lo += __shfl_xor_sync(0xffffffffu, rsum_lo, 2);
    rsum_hi += __shfl_xor_sync(0xffffffffu, rsum_hi, 1);
    rsum_hi += __shfl_xor_sync(0xffffffffu, rsum_hi, 2);

    // epilogue: normalize, pack fp16, store
    float inv_lo = 1.f / rsum_lo, inv_hi = 1.f / rsum_hi;
    int r0 = qt * 128 + wid * 16 + (lane >> 2);
    f16* oh = aout + ((size_t)b * NN + r0) * DIMM + h * DHH;
    #pragma unroll
    for (int nt = 0; nt < 8; nt++) {
        int c = nt * 8 + 2 * (lane & 3);
        *(uint32_t*)(oh + c) =
            pack2h(oacc[nt][0] * inv_lo, oacc[nt][1] * inv_lo);
        *(uint32_t*)(oh + (size_t)8 * DIMM + c) =
            pack2h(oacc[nt][2] * inv_hi, oacc[nt][3] * inv_hi);
    }
}

// ---------------- launch ----------------
extern "C" void kernel_launch(void* const* d_in, const int* in_sizes, int n_in,
                              void* d_out, int out_size)
{
    const float* x     = (const float*)d_in[0];
    const float* R     = (const float*)d_in[1];
    const float* gamma = (const float*)d_in[2];
    const float* beta  = (const float*)d_in[3];
    const float* Wqkv  = (const float*)d_in[4];
    const float* Wout  = (const float*)d_in[5];
    const float* av    = (const float*)d_in[6];
    const float* cv    = (const float*)d_in[7];
    float* out = (float*)d_out;

    f16 *xn, *wq, *wo, *qq, *kk, *vv, *aa;
    cudaGetSymbolAddress((void**)&xn, g_xn);
    cudaGetSymbolAddress((void**)&wq, g_wq);   cudaGetSymbolAddress((void**)&wo, g_wo);
    cudaGetSymbolAddress((void**)&qq, g_q);    cudaGetSymbolAddress((void**)&kk, g_k);
    cudaGetSymbolAddress((void**)&vv, g_v);    cudaGetSymbolAddress((void**)&aa, g_a);

    cudaFuncSetAttribute((const void*)mma_gemm<true>,
                         cudaFuncAttributeMaxDynamicSharedMemorySize, GEMM_SMEM);
    cudaFuncSetAttribute((const void*)mma_gemm<false>,
                         cudaFuncAttributeMaxDynamicSharedMemorySize, GEMM_SMEM);
    cudaFuncSetAttribute((const void*)flash_mma,
                         cudaFuncAttributeMaxDynamicSharedMemorySize, FLASH_SMEM);

    // 1) LayerNorm -> fp16
    ln_kernel<<<ROWS, 256>>>(x, gamma, beta, xn);

    // 2) weight transpose -> fp16
    wtrans_kernel<<<dim3(QKVN / 32, DIMM / 32), dim3(32, 8)>>>(Wqkv, wq, DIMM, QKVN);
    wtrans_kernel<<<dim3(DIMM / 32, DIMM / 32), dim3(32, 8)>>>(Wout, wo, DIMM, DIMM);

    // 3) QKV projection (1-term), scatter q/k/v fp16
    mma_gemm<true><<<dim3(QKVN / 128, ROWS / 128), 256, GEMM_SMEM>>>(
        xn, wq, nullptr, QKVN, DIMM, qq, kk, vv);

    // 4) flash attention (1-term)
    flash_mma<<<BB * HH * 16, 256, FLASH_SMEM>>>(qq, kk, vv, R, av, cv, aa);

    // 5) output projection (1-term) -> d_out fp32
    mma_gemm<false><<<dim3(DIMM / 128, ROWS / 128), 256, GEMM_SMEM>>>(
        aa, wo, out, DIMM, DIMM, nullptr, nullptr, nullptr);
}

// round 10
// speedup vs baseline: 2.6431x; 1.0436x over previous
#include <cuda_runtime.h>
#include <cuda_fp16.h>
#include <cstdint>
#include <math.h>

#define BB 4
#define NN 2048
#define DIMM 512
#define TT 16
#define HH 8
#define DHH 64
#define ROWS (BB*NN)          // 8192
#define QKVN (3*HH*DHH)       // 1536
#define HDSZ (BB*HH*NN*DHH)

typedef __half f16;

// ---------------- scratch (static device globals) ----------------
__device__ f16 g_xn[ROWS*DIMM];                      // layernorm out fp16
__device__ f16 g_wq[QKVN*DIMM];                      // W_qkv^T fp16
__device__ f16 g_wo[DIMM*DIMM];                      // W_out^T fp16
__device__ f16 g_q[HDSZ], g_k[HDSZ], g_v[HDSZ];      // Q,K,V fp16
__device__ f16 g_a[ROWS*DIMM];                       // attention out fp16

// ---------------- helpers ----------------
__device__ __forceinline__ uint32_t swz(uint32_t o) { return o ^ ((o >> 3) & 0x70u); }

__device__ __forceinline__ uint32_t smem_u32(const void* p) {
    uint32_t a;
    asm("{ .reg .u64 t; cvta.to.shared.u64 t, %1; cvt.u32.u64 %0, t; }" : "=r"(a) : "l"(p));
    return a;
}

__device__ __forceinline__ uint32_t pack2h(float lo, float hi) {
    uint32_t r;
    asm("cvt.rn.f16x2.f32 %0, %1, %2;" : "=r"(r) : "f"(hi), "f"(lo));
    return r;
}
__device__ __forceinline__ float ex2f(float x) {
    float y;
    asm("ex2.approx.f32 %0, %1;" : "=f"(y) : "f"(x));
    return y;
}

__device__ __forceinline__ void ldsm_x4(uint32_t* r, uint32_t addr) {
    asm volatile("ldmatrix.sync.aligned.m8n8.x4.shared.b16 {%0,%1,%2,%3}, [%4];"
        : "=r"(r[0]), "=r"(r[1]), "=r"(r[2]), "=r"(r[3]) : "r"(addr));
}
__device__ __forceinline__ void ldsm_x4t(uint32_t* r, uint32_t addr) {
    asm volatile("ldmatrix.sync.aligned.m8n8.x4.trans.shared.b16 {%0,%1,%2,%3}, [%4];"
        : "=r"(r[0]), "=r"(r[1]), "=r"(r[2]), "=r"(r[3]) : "r"(addr));
}
__device__ __forceinline__ void mma16816(float* c, const uint32_t* a, const uint32_t* b) {
    asm volatile("mma.sync.aligned.m16n8k16.row.col.f32.f16.f16.f32 "
        "{%0,%1,%2,%3}, {%4,%5,%6,%7}, {%8,%9}, {%0,%1,%2,%3};"
        : "+f"(c[0]), "+f"(c[1]), "+f"(c[2]), "+f"(c[3])
        : "r"(a[0]), "r"(a[1]), "r"(a[2]), "r"(a[3]), "r"(b[0]), "r"(b[1]));
}
__device__ __forceinline__ void cp16(uint32_t dst, const void* src) {
    asm volatile("cp.async.cg.shared.global [%0], [%1], 16;" :: "r"(dst), "l"(src) : "memory");
}
#define CP_COMMIT() asm volatile("cp.async.commit_group;" ::: "memory")
#define CP_WAIT1()  asm volatile("cp.async.wait_group 1;" ::: "memory")
#define CP_WAIT0()  asm volatile("cp.async.wait_group 0;" ::: "memory")

// ---------------- LayerNorm -> fp16 ----------------
__global__ void __launch_bounds__(256) ln_kernel(const float* __restrict__ x,
                                                 const float* __restrict__ gamma,
                                                 const float* __restrict__ beta,
                                                 f16* __restrict__ xn)
{
    int row = blockIdx.x;
    int t = threadIdx.x;
    const float2* xr = (const float2*)(x + (size_t)row * DIMM);
    float2 v = xr[t];
    float s = v.x + v.y, ss = v.x*v.x + v.y*v.y;
    #pragma unroll
    for (int o = 16; o > 0; o >>= 1) {
        s  += __shfl_xor_sync(0xffffffffu, s,  o);
        ss += __shfl_xor_sync(0xffffffffu, ss, o);
    }
    __shared__ float ws[8], wss[8];
    int w = t >> 5, lane = t & 31;
    if (lane == 0) { ws[w] = s; wss[w] = ss; }
    __syncthreads();
    if (w == 0) {
        s  = (lane < 8) ? ws[lane]  : 0.f;
        ss = (lane < 8) ? wss[lane] : 0.f;
        #pragma unroll
        for (int o = 4; o > 0; o >>= 1) {
            s  += __shfl_xor_sync(0xffffffffu, s,  o);
            ss += __shfl_xor_sync(0xffffffffu, ss, o);
        }
        if (lane == 0) { ws[0] = s; wss[0] = ss; }
    }
    __syncthreads();
    s = ws[0]; ss = wss[0];
    float mu  = s * (1.0f / DIMM);
    float var = ss * (1.0f / DIMM) - mu * mu;
    float inv = rsqrtf(var + 1e-5f);
    float2 g = ((const float2*)gamma)[t];
    float2 be = ((const float2*)beta)[t];
    float o0 = (v.x - mu) * inv * g.x + be.x;
    float o1 = (v.y - mu) * inv * g.y + be.y;
    ((uint32_t*)(xn + (size_t)row * DIMM))[t] = pack2h(o0, o1);
}

// ---------------- coalesced transpose -> fp16 ----------------
__global__ void __launch_bounds__(256) wtrans_kernel(const float* __restrict__ W,
                                                     f16* __restrict__ oh,
                                                     int Kd, int Nd)
{
    __shared__ float t[32][33];
    int tx = threadIdx.x, ty = threadIdx.y;
    int n0 = blockIdx.x * 32, k0 = blockIdx.y * 32;
    #pragma unroll
    for (int i = 0; i < 4; i++)
        t[ty + 8 * i][tx] = W[(size_t)(k0 + ty + 8 * i) * Nd + n0 + tx];
    __syncthreads();
    #pragma unroll
    for (int i = 0; i < 4; i++) {
        int n = n0 + ty + 8 * i, k = k0 + tx;
        oh[(size_t)n * Kd + k] = __float2half(t[tx][ty + 8 * i]);
    }
}

// ---------------- HMMA GEMM: C[M,N] = A[M,K] @ B[N,K]^T (1-term fp16) ----------------
// CTA 128x256, 8 warps (2x4), warp tile 64x64, K chunk 64, 2-stage cp.async.
// stage: A 16KB + B 32KB = 48KB; 2 stages = 96KB. 1 CTA/SM (BW-bound, not latency).
#define GA 0
#define GB 16384
#define GSTAGE 49152
#define GEMM_SMEM (2*GSTAGE)   // 98304

template<bool SCATTER>
__global__ void __launch_bounds__(256, 1)
mma_gemm(const f16* __restrict__ A, const f16* __restrict__ B,
         float* __restrict__ C, int Ncols, int K,
         f16* qo, f16* ko, f16* vo)
{
    extern __shared__ char smc[];
    uint32_t sb = smem_u32(smc);
    int tid = threadIdx.x, lane = tid & 31, wid = tid >> 5;
    int n0 = blockIdx.x * 256, m0 = blockIdx.y * 128;
    int m0w = (wid >> 2) * 64, n0w = (wid & 3) * 64;

    const f16* srcA = A + (size_t)m0 * K;
    const f16* srcB = B + (size_t)n0 * K;

    auto load_chunk = [&](int kc, int st) {
        uint32_t base = sb + st * GSTAGE;
        int kofs = kc * 64;
        #pragma unroll
        for (int i = 0; i < 4; i++) {          // A: 1024 granules
            int u = tid + i * 256;
            int row = u >> 3, g = u & 7;
            cp16(base + GA + swz(row * 128 + g * 16),
                 srcA + (size_t)row * K + kofs + g * 8);
        }
        #pragma unroll
        for (int i = 0; i < 8; i++) {          // B: 2048 granules
            int u = tid + i * 256;
            int row = u >> 3, g = u & 7;
            cp16(base + GB + swz(row * 128 + g * 16),
                 srcB + (size_t)row * K + kofs + g * 8);
        }
        CP_COMMIT();
    };

    float acc[4][8][4];
    #pragma unroll
    for (int a = 0; a < 4; a++)
        #pragma unroll
        for (int b = 0; b < 8; b++)
            #pragma unroll
            for (int c = 0; c < 4; c++) acc[a][b][c] = 0.f;

    int nch = K >> 6;
    load_chunk(0, 0);
    if (nch > 1) load_chunk(1, 1);
    for (int kc = 0; kc < nch; kc++) {
        if (kc + 1 < nch) { CP_WAIT1(); } else { CP_WAIT0(); }
        __syncthreads();
        uint32_t bs = sb + (kc & 1) * GSTAGE;
        #pragma unroll
        for (int kt = 0; kt < 4; kt++) {
            uint32_t af[4][4];
            #pragma unroll
            for (int mt = 0; mt < 4; mt++) {
                uint32_t byte = swz((m0w + mt * 16 + (lane & 15)) * 128 +
                                    kt * 32 + (lane >> 4) * 16);
                ldsm_x4(af[mt], bs + GA + byte);
            }
            #pragma unroll
            for (int p = 0; p < 4; p++) {
                uint32_t byte = swz((n0w + p * 16 + (lane & 7) + ((lane >> 4) << 3)) * 128 +
                                    kt * 32 + ((lane >> 3) & 1) * 16);
                uint32_t bf[4];
                ldsm_x4(bf, bs + GB + byte);
                #pragma unroll
                for (int mt = 0; mt < 4; mt++)
                    #pragma unroll
                    for (int half = 0; half < 2; half++) {
                        int nt = p * 2 + half;
                        mma16816(acc[mt][nt], af[mt], &bf[half * 2]);
                    }
            }
        }
        __syncthreads();
        if (kc + 2 < nch) load_chunk(kc + 2, kc & 1);
    }

    // epilogue
    int rbase = m0 + m0w + (lane >> 2);
    int cbase = n0 + n0w + 2 * (lane & 3);
    #pragma unroll
    for (int mt = 0; mt < 4; mt++) {
        #pragma unroll
        for (int nt = 0; nt < 8; nt++) {
            #pragma unroll
            for (int half = 0; half < 2; half++) {
                int r = rbase + mt * 16 + half * 8;
                int cc = cbase + nt * 8;
                float f0 = acc[mt][nt][half * 2], f1 = acc[mt][nt][half * 2 + 1];
                if (SCATTER) {
                    uint32_t hp = pack2h(f0, f1);
                    int b = r >> 11, n = r & 2047;
                    int part = cc >> 9, h = (cc >> 6) & 7, d = cc & 63;
                    size_t idx = (((size_t)(b * HH + h)) * NN + n) * DHH + d;
                    f16* dst = (part == 0) ? qo : ((part == 1) ? ko : vo);
                    *(uint32_t*)(dst + idx) = hp;
                } else {
                    float2 o2; o2.x = f0; o2.y = f1;
                    *(float2*)(C + (size_t)r * Ncols + cc) = o2;
                }
            }
        }
    }
}

// ---------------- HMMA flash attention (fp16, 4 warps x 32 q-rows) ----------------
// Warp w owns q-rows [w*32, w*32+32): K/V re-read redundancy 4x (was 8x).
// S computed in two 32-kv-col chunks (sacc stays 32 regs, P stays in regs).
// KV tiles of 64 rows, 2-stage ring; smem = Q 16KB + 2*16KB = 48KB; 2 CTAs/SM.
#define FQ 0
#define FKV 16384
#define FSTAGE 16384
#define FLASH_SMEM (FKV + 2*FSTAGE)   // 49152

__global__ void __launch_bounds__(128, 2)
flash_mma(const f16* __restrict__ qq, const f16* __restrict__ kk,
          const f16* __restrict__ vv,
          const float* __restrict__ Rg,
          const float* __restrict__ avec, const float* __restrict__ cvec,
          f16* __restrict__ aout)
{
    extern __shared__ char smc[];
    uint32_t sb = smem_u32(smc);
    int tid = threadIdx.x, lane = tid & 31, wid = tid >> 5;
    int bid = blockIdx.x;
    int qt = bid & 15, h = (bid >> 4) & 7, b = bid >> 7;
    int bh = b * HH + h;

    float aa = fabsf(avec[h]);
    float ca = fabsf(cvec[h]);

    // 64-row KV tile: K + V = 1024 granules -> 8/thread (128 threads)
    auto load_kv = [&](int jt, int st) {
        size_t o = ((size_t)bh * NN + jt * 64) * DHH;
        const f16* s2[2] = {kk + o, vv + o};
        uint32_t base = sb + FKV + st * FSTAGE;
        #pragma unroll
        for (int t = 0; t < 2; t++) {
            #pragma unroll
            for (int i = 0; i < 4; i++) {
                int u = tid + i * 128;
                int row = u >> 3, g = u & 7;
                cp16(base + t * 8192 + swz(row * 128 + g * 16),
                     s2[t] + (size_t)row * DHH + g * 8);
            }
        }
        CP_COMMIT();
    };

    // Q tile -> smem (bundled into group 0 with kv0): 1024 granules -> 8/thread
    {
        size_t qo = ((size_t)bh * NN + qt * 128) * DHH;
        #pragma unroll
        for (int i = 0; i < 8; i++) {
            int u = tid + i * 128;
            int row = u >> 3, g = u & 7;
            cp16(sb + FQ + swz(row * 128 + g * 16),
                 qq + qo + (size_t)row * DHH + g * 8);
        }
    }
    load_kv(0, 0);
    load_kv(1, 1);

    CP_WAIT1();
    __syncthreads();

    // hoist Q fragments (32 rows per warp) into registers
    uint32_t qa[4][2][4];
    #pragma unroll
    for (int kt = 0; kt < 4; kt++)
        #pragma unroll
        for (int mt = 0; mt < 2; mt++) {
            uint32_t abyte = swz((wid * 32 + mt * 16 + (lane & 15)) * 128 +
                                 kt * 32 + (lane >> 4) * 16);
            ldsm_x4(qa[kt][mt], sb + FQ + abyte);
        }

    float oacc[2][8][4];
    #pragma unroll
    for (int mt = 0; mt < 2; mt++)
        #pragma unroll
        for (int i = 0; i < 8; i++)
            #pragma unroll
            for (int j = 0; j < 4; j++) oacc[mt][i][j] = 0.f;
    float rsum[2][2] = {{0.f, 0.f}, {0.f, 0.f}};

    for (int jt = 0; jt < 32; jt++) {
        if (jt > 0) {
            if (jt + 1 < 32) { CP_WAIT1(); } else { CP_WAIT0(); }
            __syncthreads();
        }
        uint32_t bK = sb + FKV + (jt & 1) * FSTAGE;
        uint32_t bV = bK + 8192;

        float rb = Rg[((size_t)b * TT + qt) * TT + (jt >> 1)];
        float dscale = (1.f / (1.f + __expf(aa * rb - ca))) * 0.125f * 1.44269504f;

        #pragma unroll
        for (int c = 0; c < 2; c++) {          // two 32-kv-col chunks
            // ---- S chunk = Q(32x64) @ K(32x64)^T
            float sacc[2][4][4];
            #pragma unroll
            for (int mt = 0; mt < 2; mt++)
                #pragma unroll
                for (int i = 0; i < 4; i++)
                    #pragma unroll
                    for (int j = 0; j < 4; j++) sacc[mt][i][j] = 0.f;

            #pragma unroll
            for (int kt = 0; kt < 4; kt++) {
                #pragma unroll
                for (int p = 0; p < 2; p++) {
                    int p16 = c * 2 + p;
                    uint32_t bbyte = swz((p16 * 16 + (lane & 7) + ((lane >> 4) << 3)) * 128 +
                                         kt * 32 + ((lane >> 3) & 1) * 16);
                    uint32_t kb[4];
                    ldsm_x4(kb, bK + bbyte);
                    #pragma unroll
                    for (int mt = 0; mt < 2; mt++)
                        #pragma unroll
                        for (int half = 0; half < 2; half++)
                            mma16816(sacc[mt][p * 2 + half], qa[kt][mt], &kb[half * 2]);
                }
            }

            // ---- softmax numerator (bounded logits)
            #pragma unroll
            for (int mt = 0; mt < 2; mt++)
                #pragma unroll
                for (int nt = 0; nt < 4; nt++)
                    #pragma unroll
                    for (int r = 0; r < 4; r++) {
                        float p = ex2f(fmaxf(sacc[mt][nt][r], 0.f) * dscale);
                        sacc[mt][nt][r] = p;
                        rsum[mt][r >> 1] += p;
                    }

            // ---- pack P fragments: pa[mt][g] covers k-group g (16 kv)
            uint32_t pa[2][2][4];
            #pragma unroll
            for (int mt = 0; mt < 2; mt++)
                #pragma unroll
                for (int g = 0; g < 2; g++) {
                    pa[mt][g][0] = pack2h(sacc[mt][2*g][0],   sacc[mt][2*g][1]);
                    pa[mt][g][1] = pack2h(sacc[mt][2*g][2],   sacc[mt][2*g][3]);
                    pa[mt][g][2] = pack2h(sacc[mt][2*g+1][0], sacc[mt][2*g+1][1]);
                    pa[mt][g][3] = pack2h(sacc[mt][2*g+1][2], sacc[mt][2*g+1][3]);
                }

            // ---- O += P(32x32) @ V(32x64)
            #pragma unroll
            for (int g = 0; g < 2; g++) {
                int vrow = c * 32 + g * 16;
                #pragma unroll
                for (int p = 0; p < 4; p++) {
                    uint32_t vbyte = swz((vrow + (lane & 7) + ((lane >> 3) & 1) * 8) * 128 +
                                         p * 32 + (lane >> 4) * 16);
                    uint32_t vb[4];
                    ldsm_x4t(vb, bV + vbyte);
                    #pragma unroll
                    for (int mt = 0; mt < 2; mt++)
                        #pragma unroll
                        for (int half = 0; half < 2; half++)
                            mma16816(oacc[mt][p * 2 + half], pa[mt][g], &vb[half * 2]);
                }
            }
        }

        __syncthreads();
        if (jt + 2 < 32) load_kv(jt + 2, jt & 1);
    }

    // reduce row-sums across the quad
    #pragma unroll
    for (int mt = 0; mt < 2; mt++)
        #pragma unroll
        for (int hh = 0; hh < 2; hh++) {
            rsum[mt][hh] += __shfl_xor_sync(0xffffffffu, rsum[mt][hh], 1);
            rsum[mt][hh] += __shfl_xor_sync(0xffffffffu, rsum[mt][hh], 2);
        }

    // epilogue: normalize, pack fp16, store
    int r0 = qt * 128 + wid * 32 + (lane >> 2);
    f16* ob = aout + ((size_t)b * NN + r0) * DIMM + h * DHH;
    #pragma unroll
    for (int mt = 0; mt < 2; mt++) {
        float inv_lo = 1.f / rsum[mt][0], inv_hi = 1.f / rsum[mt][1];
        f16* om = ob + (size_t)(mt * 16) * DIMM;
        #pragma unroll
        for (int nt = 0; nt < 8; nt++) {
            int c = nt * 8 + 2 * (lane & 3);
            *(uint32_t*)(om + c) =
                pack2h(oacc[mt][nt][0] * inv_lo, oacc[mt][nt][1] * inv_lo);
            *(uint32_t*)(om + (size_t)8 * DIMM + c) =
                pack2h(oacc[mt][nt][2] * inv_hi, oacc[mt][nt][3] * inv_hi);
        }
    }
}

// ---------------- launch ----------------
extern "C" void kernel_launch(void* const* d_in, const int* in_sizes, int n_in,
                              void* d_out, int out_size)
{
    const float* x     = (const float*)d_in[0];
    const float* R     = (const float*)d_in[1];
    const float* gamma = (const float*)d_in[2];
    const float* beta  = (const float*)d_in[3];
    const float* Wqkv  = (const float*)d_in[4];
    const float* Wout  = (const float*)d_in[5];
    const float* av    = (const float*)d_in[6];
    const float* cv    = (const float*)d_in[7];
    float* out = (float*)d_out;

    f16 *xn, *wq, *wo, *qq, *kk, *vv, *aa;
    cudaGetSymbolAddress((void**)&xn, g_xn);
    cudaGetSymbolAddress((void**)&wq, g_wq);   cudaGetSymbolAddress((void**)&wo, g_wo);
    cudaGetSymbolAddress((void**)&qq, g_q);    cudaGetSymbolAddress((void**)&kk, g_k);
    cudaGetSymbolAddress((void**)&vv, g_v);    cudaGetSymbolAddress((void**)&aa, g_a);

    cudaFuncSetAttribute((const void*)mma_gemm<true>,
                         cudaFuncAttributeMaxDynamicSharedMemorySize, GEMM_SMEM);
    cudaFuncSetAttribute((const void*)mma_gemm<false>,
                         cudaFuncAttributeMaxDynamicSharedMemorySize, GEMM_SMEM);
    cudaFuncSetAttribute((const void*)flash_mma,
                         cudaFuncAttributeMaxDynamicSharedMemorySize, FLASH_SMEM);

    // 1) LayerNorm -> fp16
    ln_kernel<<<ROWS, 256>>>(x, gamma, beta, xn);

    // 2) weight transpose -> fp16
    wtrans_kernel<<<dim3(QKVN / 32, DIMM / 32), dim3(32, 8)>>>(Wqkv, wq, DIMM, QKVN);
    wtrans_kernel<<<dim3(DIMM / 32, DIMM / 32), dim3(32, 8)>>>(Wout, wo, DIMM, DIMM);

    // 3) QKV projection (1-term), scatter q/k/v fp16  (grid 6x64)
    mma_gemm<true><<<dim3(QKVN / 256, ROWS / 128), 256, GEMM_SMEM>>>(
        xn, wq, nullptr, QKVN, DIMM, qq, kk, vv);

    // 4) flash attention (4 warps, 128 threads, 2 CTAs/SM)
    flash_mma<<<BB * HH * 16, 128, FLASH_SMEM>>>(qq, kk, vv, R, av, cv, aa);

    // 5) output projection (1-term) -> d_out fp32  (grid 2x64)
    mma_gemm<false><<<dim3(DIMM / 256, ROWS / 128), 256, GEMM_SMEM>>>(
        aa, wo, out, DIMM, DIMM, nullptr, nullptr, nullptr);
}

// round 11
// speedup vs baseline: 2.8808x; 1.0899x over previous
#include <cuda_runtime.h>
#include <cuda_fp16.h>
#include <cstdint>
#include <math.h>

#define BB 4
#define NN 2048
#define DIMM 512
#define TT 16
#define HH 8
#define DHH 64
#define ROWS (BB*NN)          // 8192
#define QKVN (3*HH*DHH)       // 1536
#define HDSZ (BB*HH*NN*DHH)

typedef __half f16;

// ---------------- scratch (static device globals) ----------------
__device__ f16 g_xn[ROWS*DIMM];                      // layernorm out fp16
__device__ f16 g_wq[QKVN*DIMM];                      // W_qkv^T fp16
__device__ f16 g_wo[DIMM*DIMM];                      // W_out^T fp16
__device__ f16 g_q[HDSZ], g_k[HDSZ], g_v[HDSZ];      // Q,K,V fp16
__device__ f16 g_a[ROWS*DIMM];                       // attention out fp16

// ---------------- helpers ----------------
__device__ __forceinline__ uint32_t swz(uint32_t o) { return o ^ ((o >> 3) & 0x70u); }

__device__ __forceinline__ uint32_t smem_u32(const void* p) {
    uint32_t a;
    asm("{ .reg .u64 t; cvta.to.shared.u64 t, %1; cvt.u32.u64 %0, t; }" : "=r"(a) : "l"(p));
    return a;
}

__device__ __forceinline__ uint32_t pack2h(float lo, float hi) {
    uint32_t r;
    asm("cvt.rn.f16x2.f32 %0, %1, %2;" : "=r"(r) : "f"(hi), "f"(lo));
    return r;
}
__device__ __forceinline__ float ex2f(float x) {
    float y;
    asm("ex2.approx.f32 %0, %1;" : "=f"(y) : "f"(x));
    return y;
}

__device__ __forceinline__ void ldsm_x4(uint32_t* r, uint32_t addr) {
    asm volatile("ldmatrix.sync.aligned.m8n8.x4.shared.b16 {%0,%1,%2,%3}, [%4];"
        : "=r"(r[0]), "=r"(r[1]), "=r"(r[2]), "=r"(r[3]) : "r"(addr));
}
__device__ __forceinline__ void ldsm_x4t(uint32_t* r, uint32_t addr) {
    asm volatile("ldmatrix.sync.aligned.m8n8.x4.trans.shared.b16 {%0,%1,%2,%3}, [%4];"
        : "=r"(r[0]), "=r"(r[1]), "=r"(r[2]), "=r"(r[3]) : "r"(addr));
}
__device__ __forceinline__ void mma16816(float* c, const uint32_t* a, const uint32_t* b) {
    asm volatile("mma.sync.aligned.m16n8k16.row.col.f32.f16.f16.f32 "
        "{%0,%1,%2,%3}, {%4,%5,%6,%7}, {%8,%9}, {%0,%1,%2,%3};"
        : "+f"(c[0]), "+f"(c[1]), "+f"(c[2]), "+f"(c[3])
        : "r"(a[0]), "r"(a[1]), "r"(a[2]), "r"(a[3]), "r"(b[0]), "r"(b[1]));
}
__device__ __forceinline__ void cp16(uint32_t dst, const void* src) {
    asm volatile("cp.async.cg.shared.global [%0], [%1], 16;" :: "r"(dst), "l"(src) : "memory");
}
#define CP_COMMIT() asm volatile("cp.async.commit_group;" ::: "memory")
#define CP_WAIT1()  asm volatile("cp.async.wait_group 1;" ::: "memory")
#define CP_WAIT0()  asm volatile("cp.async.wait_group 0;" ::: "memory")

// ---------------- fused prep: LayerNorm + both weight transposes ----------------
// blocks [0, 8192)           : LN row b
// blocks [8192, 8960)        : W_qkv transpose tile (48 x 16)
// blocks [8960, 9216)        : W_out transpose tile (16 x 16)
__global__ void __launch_bounds__(256) prep_kernel(const float* __restrict__ x,
                                                   const float* __restrict__ gamma,
                                                   const float* __restrict__ beta,
                                                   const float* __restrict__ Wqkv,
                                                   const float* __restrict__ Wout,
                                                   f16* __restrict__ xn)
{
    __shared__ float tsh[32 * 33];
    int blk = blockIdx.x;
    int t = threadIdx.x;

    if (blk < ROWS) {
        // ---- LayerNorm row
        int row = blk;
        const float2* xr = (const float2*)(x + (size_t)row * DIMM);
        float2 v = xr[t];
        float s = v.x + v.y, ss = v.x*v.x + v.y*v.y;
        #pragma unroll
        for (int o = 16; o > 0; o >>= 1) {
            s  += __shfl_xor_sync(0xffffffffu, s,  o);
            ss += __shfl_xor_sync(0xffffffffu, ss, o);
        }
        int w = t >> 5, lane = t & 31;
        if (lane == 0) { tsh[w] = s; tsh[8 + w] = ss; }
        __syncthreads();
        if (w == 0) {
            s  = (lane < 8) ? tsh[lane]     : 0.f;
            ss = (lane < 8) ? tsh[8 + lane] : 0.f;
            #pragma unroll
            for (int o = 4; o > 0; o >>= 1) {
                s  += __shfl_xor_sync(0xffffffffu, s,  o);
                ss += __shfl_xor_sync(0xffffffffu, ss, o);
            }
            if (lane == 0) { tsh[0] = s; tsh[8] = ss; }
        }
        __syncthreads();
        s = tsh[0]; ss = tsh[8];
        float mu  = s * (1.0f / DIMM);
        float var = ss * (1.0f / DIMM) - mu * mu;
        float inv = rsqrtf(var + 1e-5f);
        float2 g = ((const float2*)gamma)[t];
        float2 be = ((const float2*)beta)[t];
        float o0 = (v.x - mu) * inv * g.x + be.x;
        float o1 = (v.y - mu) * inv * g.y + be.y;
        ((uint32_t*)(xn + (size_t)row * DIMM))[t] = pack2h(o0, o1);
    } else {
        // ---- weight transpose tile (32x32), coalesced both sides
        const float* W;
        f16* dst;
        int Nd, Kd, idx;
        if (blk < ROWS + (QKVN / 32) * (DIMM / 32)) {
            idx = blk - ROWS;
            W = Wqkv; dst = g_wq; Nd = QKVN; Kd = DIMM;
        } else {
            idx = blk - ROWS - (QKVN / 32) * (DIMM / 32);
            W = Wout; dst = g_wo; Nd = DIMM; Kd = DIMM;
        }
        int nblk = Nd / 32;
        int n0 = (idx % nblk) * 32, k0 = (idx / nblk) * 32;
        int tx = t & 31, ty = t >> 5;
        #pragma unroll
        for (int i = 0; i < 4; i++)
            tsh[(ty + 8 * i) * 33 + tx] = W[(size_t)(k0 + ty + 8 * i) * Nd + n0 + tx];
        __syncthreads();
        #pragma unroll
        for (int i = 0; i < 4; i++) {
            int n = n0 + ty + 8 * i, k = k0 + tx;
            dst[(size_t)n * Kd + k] = __float2half(tsh[tx * 33 + ty + 8 * i]);
        }
    }
}

// ---------------- HMMA GEMM: C[M,N] = A[M,K] @ B[N,K]^T (1-term fp16) ----------------
// R9-proven config: CTA 128x128, 8 warps (2x4, warp tile 64x32), K chunk 64,
// 2-stage cp.async; stage 32KB; 2 CTAs/SM; 126 regs.
#define GA 0
#define GB 16384
#define GSTAGE 32768
#define GEMM_SMEM (2*GSTAGE)   // 65536

template<bool SCATTER>
__global__ void __launch_bounds__(256, 2)
mma_gemm(const f16* __restrict__ A, const f16* __restrict__ B,
         float* __restrict__ C, int Ncols, int K,
         f16* qo, f16* ko, f16* vo)
{
    extern __shared__ char smc[];
    uint32_t sb = smem_u32(smc);
    int tid = threadIdx.x, lane = tid & 31, wid = tid >> 5;
    int n0 = blockIdx.x * 128, m0 = blockIdx.y * 128;
    int m0w = (wid >> 2) * 64, n0w = (wid & 3) * 32;

    const f16* srcA = A + (size_t)m0 * K;
    const f16* srcB = B + (size_t)n0 * K;

    auto load_chunk = [&](int kc, int st) {
        uint32_t base = sb + st * GSTAGE;
        int kofs = kc * 64;
        #pragma unroll
        for (int i = 0; i < 4; i++) {
            int u = tid + i * 256;
            int row = u >> 3, g = u & 7;
            cp16(base + GA + swz(row * 128 + g * 16),
                 srcA + (size_t)row * K + kofs + g * 8);
        }
        #pragma unroll
        for (int i = 0; i < 4; i++) {
            int u = tid + i * 256;
            int row = u >> 3, g = u & 7;
            cp16(base + GB + swz(row * 128 + g * 16),
                 srcB + (size_t)row * K + kofs + g * 8);
        }
        CP_COMMIT();
    };

    float acc[4][4][4];
    #pragma unroll
    for (int a = 0; a < 4; a++)
        #pragma unroll
        for (int b = 0; b < 4; b++)
            #pragma unroll
            for (int c = 0; c < 4; c++) acc[a][b][c] = 0.f;

    int nch = K >> 6;
    load_chunk(0, 0);
    if (nch > 1) load_chunk(1, 1);
    for (int kc = 0; kc < nch; kc++) {
        if (kc + 1 < nch) { CP_WAIT1(); } else { CP_WAIT0(); }
        __syncthreads();
        uint32_t bs = sb + (kc & 1) * GSTAGE;
        #pragma unroll
        for (int kt = 0; kt < 4; kt++) {
            uint32_t af[4][4];
            #pragma unroll
            for (int mt = 0; mt < 4; mt++) {
                uint32_t byte = swz((m0w + mt * 16 + (lane & 15)) * 128 +
                                    kt * 32 + (lane >> 4) * 16);
                ldsm_x4(af[mt], bs + GA + byte);
            }
            #pragma unroll
            for (int p = 0; p < 2; p++) {
                uint32_t byte = swz((n0w + p * 16 + (lane & 7) + ((lane >> 4) << 3)) * 128 +
                                    kt * 32 + ((lane >> 3) & 1) * 16);
                uint32_t bf[4];
                ldsm_x4(bf, bs + GB + byte);
                #pragma unroll
                for (int mt = 0; mt < 4; mt++)
                    #pragma unroll
                    for (int half = 0; half < 2; half++) {
                        int nt = p * 2 + half;
                        mma16816(acc[mt][nt], af[mt], &bf[half * 2]);
                    }
            }
        }
        __syncthreads();
        if (kc + 2 < nch) load_chunk(kc + 2, kc & 1);
    }

    // epilogue
    int rbase = m0 + m0w + (lane >> 2);
    int cbase = n0 + n0w + 2 * (lane & 3);
    #pragma unroll
    for (int mt = 0; mt < 4; mt++) {
        #pragma unroll
        for (int nt = 0; nt < 4; nt++) {
            #pragma unroll
            for (int half = 0; half < 2; half++) {
                int r = rbase + mt * 16 + half * 8;
                int cc = cbase + nt * 8;
                float f0 = acc[mt][nt][half * 2], f1 = acc[mt][nt][half * 2 + 1];
                if (SCATTER) {
                    uint32_t hp = pack2h(f0, f1);
                    int b = r >> 11, n = r & 2047;
                    int part = cc >> 9, h = (cc >> 6) & 7, d = cc & 63;
                    size_t idx = (((size_t)(b * HH + h)) * NN + n) * DHH + d;
                    f16* dst = (part == 0) ? qo : ((part == 1) ? ko : vo);
                    *(uint32_t*)(dst + idx) = hp;
                } else {
                    float2 o2; o2.x = f0; o2.y = f1;
                    *(float2*)(C + (size_t)r * Ncols + cc) = o2;
                }
            }
        }
    }
}

// ---------------- HMMA flash attention (fp16, 4 warps x 32 q-rows) ----------------
// R10-proven config: warp owns 32 q-rows, K/V redundancy 4x, two 32-kv-col chunks,
// KV 64-row tiles, 2-stage ring, smem 48KB, 2 CTAs/SM.
#define FQ 0
#define FKV 16384
#define FSTAGE 16384
#define FLASH_SMEM (FKV + 2*FSTAGE)   // 49152

__global__ void __launch_bounds__(128, 2)
flash_mma(const f16* __restrict__ qq, const f16* __restrict__ kk,
          const f16* __restrict__ vv,
          const float* __restrict__ Rg,
          const float* __restrict__ avec, const float* __restrict__ cvec,
          f16* __restrict__ aout)
{
    extern __shared__ char smc[];
    uint32_t sb = smem_u32(smc);
    int tid = threadIdx.x, lane = tid & 31, wid = tid >> 5;
    int bid = blockIdx.x;
    int qt = bid & 15, h = (bid >> 4) & 7, b = bid >> 7;
    int bh = b * HH + h;

    float aa = fabsf(avec[h]);
    float ca = fabsf(cvec[h]);

    auto load_kv = [&](int jt, int st) {
        size_t o = ((size_t)bh * NN + jt * 64) * DHH;
        const f16* s2[2] = {kk + o, vv + o};
        uint32_t base = sb + FKV + st * FSTAGE;
        #pragma unroll
        for (int t = 0; t < 2; t++) {
            #pragma unroll
            for (int i = 0; i < 4; i++) {
                int u = tid + i * 128;
                int row = u >> 3, g = u & 7;
                cp16(base + t * 8192 + swz(row * 128 + g * 16),
                     s2[t] + (size_t)row * DHH + g * 8);
            }
        }
        CP_COMMIT();
    };

    // Q tile -> smem (bundled into group 0 with kv0)
    {
        size_t qo = ((size_t)bh * NN + qt * 128) * DHH;
        #pragma unroll
        for (int i = 0; i < 8; i++) {
            int u = tid + i * 128;
            int row = u >> 3, g = u & 7;
            cp16(sb + FQ + swz(row * 128 + g * 16),
                 qq + qo + (size_t)row * DHH + g * 8);
        }
    }
    load_kv(0, 0);
    load_kv(1, 1);

    CP_WAIT1();
    __syncthreads();

    // hoist Q fragments (32 rows per warp)
    uint32_t qa[4][2][4];
    #pragma unroll
    for (int kt = 0; kt < 4; kt++)
        #pragma unroll
        for (int mt = 0; mt < 2; mt++) {
            uint32_t abyte = swz((wid * 32 + mt * 16 + (lane & 15)) * 128 +
                                 kt * 32 + (lane >> 4) * 16);
            ldsm_x4(qa[kt][mt], sb + FQ + abyte);
        }

    float oacc[2][8][4];
    #pragma unroll
    for (int mt = 0; mt < 2; mt++)
        #pragma unroll
        for (int i = 0; i < 8; i++)
            #pragma unroll
            for (int j = 0; j < 4; j++) oacc[mt][i][j] = 0.f;
    float rsum[2][2] = {{0.f, 0.f}, {0.f, 0.f}};

    for (int jt = 0; jt < 32; jt++) {
        if (jt > 0) {
            if (jt + 1 < 32) { CP_WAIT1(); } else { CP_WAIT0(); }
            __syncthreads();
        }
        uint32_t bK = sb + FKV + (jt & 1) * FSTAGE;
        uint32_t bV = bK + 8192;

        float rb = Rg[((size_t)b * TT + qt) * TT + (jt >> 1)];
        float dscale = (1.f / (1.f + __expf(aa * rb - ca))) * 0.125f * 1.44269504f;

        #pragma unroll
        for (int c = 0; c < 2; c++) {          // two 32-kv-col chunks
            float sacc[2][4][4];
            #pragma unroll
            for (int mt = 0; mt < 2; mt++)
                #pragma unroll
                for (int i = 0; i < 4; i++)
                    #pragma unroll
                    for (int j = 0; j < 4; j++) sacc[mt][i][j] = 0.f;

            #pragma unroll
            for (int kt = 0; kt < 4; kt++) {
                #pragma unroll
                for (int p = 0; p < 2; p++) {
                    int p16 = c * 2 + p;
                    uint32_t bbyte = swz((p16 * 16 + (lane & 7) + ((lane >> 4) << 3)) * 128 +
                                         kt * 32 + ((lane >> 3) & 1) * 16);
                    uint32_t kb[4];
                    ldsm_x4(kb, bK + bbyte);
                    #pragma unroll
                    for (int mt = 0; mt < 2; mt++)
                        #pragma unroll
                        for (int half = 0; half < 2; half++)
                            mma16816(sacc[mt][p * 2 + half], qa[kt][mt], &kb[half * 2]);
                }
            }

            // softmax numerator (bounded logits)
            #pragma unroll
            for (int mt = 0; mt < 2; mt++)
                #pragma unroll
                for (int nt = 0; nt < 4; nt++)
                    #pragma unroll
                    for (int r = 0; r < 4; r++) {
                        float p = ex2f(fmaxf(sacc[mt][nt][r], 0.f) * dscale);
                        sacc[mt][nt][r] = p;
                        rsum[mt][r >> 1] += p;
                    }

            // pack P fragments
            uint32_t pa[2][2][4];
            #pragma unroll
            for (int mt = 0; mt < 2; mt++)
                #pragma unroll
                for (int g = 0; g < 2; g++) {
                    pa[mt][g][0] = pack2h(sacc[mt][2*g][0],   sacc[mt][2*g][1]);
                    pa[mt][g][1] = pack2h(sacc[mt][2*g][2],   sacc[mt][2*g][3]);
                    pa[mt][g][2] = pack2h(sacc[mt][2*g+1][0], sacc[mt][2*g+1][1]);
                    pa[mt][g][3] = pack2h(sacc[mt][2*g+1][2], sacc[mt][2*g+1][3]);
                }

            // O += P(32x32) @ V(32x64)
            #pragma unroll
            for (int g = 0; g < 2; g++) {
                int vrow = c * 32 + g * 16;
                #pragma unroll
                for (int p = 0; p < 4; p++) {
                    uint32_t vbyte = swz((vrow + (lane & 7) + ((lane >> 3) & 1) * 8) * 128 +
                                         p * 32 + (lane >> 4) * 16);
                    uint32_t vb[4];
                    ldsm_x4t(vb, bV + vbyte);
                    #pragma unroll
                    for (int mt = 0; mt < 2; mt++)
                        #pragma unroll
                        for (int half = 0; half < 2; half++)
                            mma16816(oacc[mt][p * 2 + half], pa[mt][g], &vb[half * 2]);
                }
            }
        }

        __syncthreads();
        if (jt + 2 < 32) load_kv(jt + 2, jt & 1);
    }

    // reduce row-sums across the quad
    #pragma unroll
    for (int mt = 0; mt < 2; mt++)
        #pragma unroll
        for (int hh = 0; hh < 2; hh++) {
            rsum[mt][hh] += __shfl_xor_sync(0xffffffffu, rsum[mt][hh], 1);
            rsum[mt][hh] += __shfl_xor_sync(0xffffffffu, rsum[mt][hh], 2);
        }

    // epilogue
    int r0 = qt * 128 + wid * 32 + (lane >> 2);
    f16* ob = aout + ((size_t)b * NN + r0) * DIMM + h * DHH;
    #pragma unroll
    for (int mt = 0; mt < 2; mt++) {
        float inv_lo = 1.f / rsum[mt][0], inv_hi = 1.f / rsum[mt][1];
        f16* om = ob + (size_t)(mt * 16) * DIMM;
        #pragma unroll
        for (int nt = 0; nt < 8; nt++) {
            int c = nt * 8 + 2 * (lane & 3);
            *(uint32_t*)(om + c) =
                pack2h(oacc[mt][nt][0] * inv_lo, oacc[mt][nt][1] * inv_lo);
            *(uint32_t*)(om + (size_t)8 * DIMM + c) =
                pack2h(oacc[mt][nt][2] * inv_hi, oacc[mt][nt][3] * inv_hi);
        }
    }
}

// ---------------- launch ----------------
extern "C" void kernel_launch(void* const* d_in, const int* in_sizes, int n_in,
                              void* d_out, int out_size)
{
    const float* x     = (const float*)d_in[0];
    const float* R     = (const float*)d_in[1];
    const float* gamma = (const float*)d_in[2];
    const float* beta  = (const float*)d_in[3];
    const float* Wqkv  = (const float*)d_in[4];
    const float* Wout  = (const float*)d_in[5];
    const float* av    = (const float*)d_in[6];
    const float* cv    = (const float*)d_in[7];
    float* out = (float*)d_out;

    f16 *xn, *wq, *wo, *qq, *kk, *vv, *aa;
    cudaGetSymbolAddress((void**)&xn, g_xn);
    cudaGetSymbolAddress((void**)&wq, g_wq);   cudaGetSymbolAddress((void**)&wo, g_wo);
    cudaGetSymbolAddress((void**)&qq, g_q);    cudaGetSymbolAddress((void**)&kk, g_k);
    cudaGetSymbolAddress((void**)&vv, g_v);    cudaGetSymbolAddress((void**)&aa, g_a);

    cudaFuncSetAttribute((const void*)mma_gemm<true>,
                         cudaFuncAttributeMaxDynamicSharedMemorySize, GEMM_SMEM);
    cudaFuncSetAttribute((const void*)mma_gemm<false>,
                         cudaFuncAttributeMaxDynamicSharedMemorySize, GEMM_SMEM);
    cudaFuncSetAttribute((const void*)flash_mma,
                         cudaFuncAttributeMaxDynamicSharedMemorySize, FLASH_SMEM);

    // 1) fused prep: LayerNorm + weight transposes (one launch)
    int prep_blocks = ROWS + (QKVN / 32) * (DIMM / 32) + (DIMM / 32) * (DIMM / 32);
    prep_kernel<<<prep_blocks, 256>>>(x, gamma, beta, Wqkv, Wout, xn);

    // 2) QKV projection (1-term), scatter q/k/v fp16  (grid 12x64, 2 CTAs/SM)
    mma_gemm<true><<<dim3(QKVN / 128, ROWS / 128), 256, GEMM_SMEM>>>(
        xn, wq, nullptr, QKVN, DIMM, qq, kk, vv);

    // 3) flash attention (4 warps, 128 threads, 2 CTAs/SM)
    flash_mma<<<BB * HH * 16, 128, FLASH_SMEM>>>(qq, kk, vv, R, av, cv, aa);

    // 4) output projection (1-term) -> d_out fp32  (grid 4x64, 2 CTAs/SM)
    mma_gemm<false><<<dim3(DIMM / 128, ROWS / 128), 256, GEMM_SMEM>>>(
        aa, wo, out, DIMM, DIMM, nullptr, nullptr, nullptr);
}